// round 2
// baseline (speedup 1.0000x reference)
#include <cuda_runtime.h>
#include <math.h>

#define H 64
#define NN 12000
#define NE 50000
#define EHD 128          // 2H
#define QC 8192          // H * 2H

// ---------------- scratch (device globals; allocation-free) ----------------
__device__ float g_eh[NE * EHD];          // 25.6 MB  relu(edge@W1.T+b1)
__device__ float g_agg[NN * H];           // 3 MB     scatter-sum target
__device__ float g_bb[NN * H];            // 3 MB     per-node b2 bias term
__device__ float g_WihT[64 * 192];        // transposed GRU weights
__device__ float g_WhhT[64 * 192];
__device__ int   g_cnt[NN];
__device__ int   g_off[NN + 1];
__device__ int   g_cur[NN];
__device__ int   g_elist[NE];

// packed f32x2 helpers
__device__ __forceinline__ unsigned long long pack_dup(float a) {
    unsigned long long r;
    asm("mov.b64 %0, {%1, %1};" : "=l"(r) : "f"(a));
    return r;
}
__device__ __forceinline__ void fma2(unsigned long long& acc, unsigned long long a,
                                     unsigned long long b) {
    asm("fma.rn.f32x2 %0, %1, %2, %3;" : "=l"(acc) : "l"(a), "l"(b), "l"(acc));
}
__device__ __forceinline__ void unpack2(unsigned long long v, float& lo, float& hi) {
    asm("mov.b64 {%0, %1}, %2;" : "=f"(lo), "=f"(hi) : "l"(v));
}

// ---------------- 0: zero agg + counts ----------------
__global__ void zero_kernel() {
    int i = blockIdx.x * blockDim.x + threadIdx.x;
    int stride = gridDim.x * blockDim.x;
    for (int j = i; j < NN * H; j += stride) g_agg[j] = 0.f;
    for (int j = i; j < NN; j += stride) g_cnt[j] = 0;
}

// ---------------- 1: eh = relu(edge @ W1.T + b1), tiled GEMM ----------------
// M=NE, N=128, K=64. CTA = 128 edges x 128 outputs.
__global__ __launch_bounds__(256, 2) void eh_gemm(const float* __restrict__ edge,
                                                  const float* __restrict__ W1,
                                                  const float* __restrict__ b1) {
    extern __shared__ float dyn[];
    float* As = dyn;           // [64][128]  edge tile, k-major
    float* Bs = dyn + 8192;    // [64][128]  Bs[k*128+n] = W1[n*64+k]
    int m0 = blockIdx.x * 128;
    int tid = threadIdx.x;

    for (int i = tid; i < 2048; i += 256) {
        int r = i >> 4, c4 = i & 15;
        float4 v = make_float4(0.f, 0.f, 0.f, 0.f);
        int m = m0 + r;
        if (m < NE) v = reinterpret_cast<const float4*>(edge)[m * 16 + c4];
        As[(c4 * 4 + 0) * 128 + r] = v.x;
        As[(c4 * 4 + 1) * 128 + r] = v.y;
        As[(c4 * 4 + 2) * 128 + r] = v.z;
        As[(c4 * 4 + 3) * 128 + r] = v.w;
    }
    for (int i = tid; i < 8192; i += 256) {
        int n = i & 127, k = i >> 7;
        Bs[k * 128 + n] = W1[n * 64 + k];
    }
    __syncthreads();

    int tx = tid & 15, ty = tid >> 4;
    int mr = ty * 8, nc = tx * 8;
    unsigned long long acc2[8][4];
#pragma unroll
    for (int i = 0; i < 8; i++)
#pragma unroll
        for (int jj = 0; jj < 4; jj++) acc2[i][jj] = 0ull;

#pragma unroll 8
    for (int k = 0; k < 64; k++) {
        float a[8];
        *(float4*)&a[0] = *(const float4*)&As[k * 128 + mr];
        *(float4*)&a[4] = *(const float4*)&As[k * 128 + mr + 4];
        ulonglong2 b01 = *(const ulonglong2*)&Bs[k * 128 + nc];
        ulonglong2 b23 = *(const ulonglong2*)&Bs[k * 128 + nc + 4];
        unsigned long long bq[4] = {b01.x, b01.y, b23.x, b23.y};
#pragma unroll
        for (int i = 0; i < 8; i++) {
            unsigned long long ad = pack_dup(a[i]);
#pragma unroll
            for (int jj = 0; jj < 4; jj++) fma2(acc2[i][jj], ad, bq[jj]);
        }
    }

    float bias[8];
#pragma unroll
    for (int j = 0; j < 8; j++) bias[j] = b1[nc + j];

#pragma unroll
    for (int i = 0; i < 8; i++) {
        int m = m0 + mr + i;
        if (m < NE) {
            float o[8];
#pragma unroll
            for (int jj = 0; jj < 4; jj++) unpack2(acc2[i][jj], o[2 * jj], o[2 * jj + 1]);
#pragma unroll
            for (int j = 0; j < 8; j++) o[j] = fmaxf(o[j] + bias[j], 0.f);
            float* dst = g_eh + (size_t)m * EHD + nc;
            *(float4*)dst = *(float4*)&o[0];
            *(float4*)(dst + 4) = *(float4*)&o[4];
        }
    }
}

// ---------------- 2: per-node b2 bias: g_bb[n,k] = sum_h node[n,h]*b2[h*64+k] --
__global__ __launch_bounds__(256) void bb_kernel(const float* __restrict__ node,
                                                 const float* __restrict__ b2) {
    __shared__ float b2s[4096];   // [h][k]
    __shared__ float xs[4][64];
    int tid = threadIdx.x;
    for (int i = tid; i < 4096; i += 256) b2s[i] = b2[i];
    int sub = tid >> 6, k = tid & 63;
    __syncthreads();
    for (int n0 = blockIdx.x * 4; n0 < NN; n0 += gridDim.x * 4) {
        int n = n0 + sub;   // NN % 4 == 0
        xs[sub][k] = node[n * 64 + k];
        __syncthreads();
        float acc = 0.f;
#pragma unroll 8
        for (int h = 0; h < 64; h++) acc = fmaf(xs[sub][h], b2s[h * 64 + k], acc);
        g_bb[n * 64 + k] = acc;
        __syncthreads();
    }
}

// ---------------- 3: CSR by src ----------------
__global__ void count_kernel(const int* __restrict__ src) {
    int e = blockIdx.x * blockDim.x + threadIdx.x;
    if (e < NE) atomicAdd(&g_cnt[src[e]], 1);
}

__global__ void scan_kernel() {
    __shared__ int sm[1024];
    int tid = threadIdx.x;
    const int C = 12;   // 1024*12 >= NN
    int base = tid * C;
    int loc[C];
    int s = 0;
#pragma unroll
    for (int i = 0; i < C; i++) {
        int v = (base + i < NN) ? g_cnt[base + i] : 0;
        loc[i] = s;
        s += v;
    }
    sm[tid] = s;
    __syncthreads();
    for (int d = 1; d < 1024; d <<= 1) {
        int v = (tid >= d) ? sm[tid - d] : 0;
        __syncthreads();
        if (tid >= d) sm[tid] += v;
        __syncthreads();
    }
    int ex = sm[tid] - s;
#pragma unroll
    for (int i = 0; i < C; i++) {
        if (base + i < NN) {
            g_off[base + i] = ex + loc[i];
            g_cur[base + i] = ex + loc[i];
        }
    }
    if (tid == 1023) g_off[NN] = sm[1023];
}

__global__ void scatter_kernel(const int* __restrict__ src) {
    int e = blockIdx.x * blockDim.x + threadIdx.x;
    if (e < NE) {
        int p = atomicAdd(&g_cur[src[e]], 1);
        g_elist[p] = e;
    }
}

// ---------------- 4: FUSED q-GEMM + message + scatter-add ----------------
// CTA (kblk, my): computes q-block q[m0..m0+127, kblk*128 .. +127] in SMEM,
// then for each edge e with src in tile: msg[e,kblk] = dot(eh[e,:], qs[src,:]),
// atomicAdd into g_agg[dst[e]*64 + kblk] (+ precomputed b2 bias).
__global__ __launch_bounds__(256, 2) void fused_qmsg(const float* __restrict__ node,
                                                     const float* __restrict__ W2,
                                                     const int* __restrict__ src,
                                                     const int* __restrict__ dst) {
    extern __shared__ float dyn[];
    float* As = dyn;          // [64][128]  node tile, k-major (32KB)
    float* Bs = dyn + 8192;   // [64][128]  W2 slice (32KB)
    int kblk = blockIdx.x;          // 0..63
    int m0 = blockIdx.y * 128;
    int n0 = kblk * 128;
    int tid = threadIdx.x;

    for (int i = tid; i < 2048; i += 256) {
        int r = i >> 4, c4 = i & 15;
        float4 v = make_float4(0.f, 0.f, 0.f, 0.f);
        int m = m0 + r;
        if (m < NN) v = reinterpret_cast<const float4*>(node)[m * 16 + c4];
        As[(c4 * 4 + 0) * 128 + r] = v.x;
        As[(c4 * 4 + 1) * 128 + r] = v.y;
        As[(c4 * 4 + 2) * 128 + r] = v.z;
        As[(c4 * 4 + 3) * 128 + r] = v.w;
    }
    for (int i = tid; i < 2048; i += 256) {
        int r = i >> 5, c4 = i & 31;
        reinterpret_cast<float4*>(Bs)[r * 32 + c4] =
            reinterpret_cast<const float4*>(W2)[r * 2048 + (n0 >> 2) + c4];
    }
    __syncthreads();

    int tx = tid & 15, ty = tid >> 4;
    int mr = ty * 8, nc = tx * 8;
    unsigned long long acc2[8][4];
#pragma unroll
    for (int i = 0; i < 8; i++)
#pragma unroll
        for (int jj = 0; jj < 4; jj++) acc2[i][jj] = 0ull;

#pragma unroll 8
    for (int k = 0; k < 64; k++) {
        float a[8];
        *(float4*)&a[0] = *(const float4*)&As[k * 128 + mr];
        *(float4*)&a[4] = *(const float4*)&As[k * 128 + mr + 4];
        ulonglong2 b01 = *(const ulonglong2*)&Bs[k * 128 + nc];
        ulonglong2 b23 = *(const ulonglong2*)&Bs[k * 128 + nc + 4];
        unsigned long long bq[4] = {b01.x, b01.y, b23.x, b23.y};
#pragma unroll
        for (int i = 0; i < 8; i++) {
            unsigned long long ad = pack_dup(a[i]);
#pragma unroll
            for (int jj = 0; jj < 4; jj++) fma2(acc2[i][jj], ad, bq[jj]);
        }
    }
    __syncthreads();   // everyone done reading As/Bs

    // write q-block into smem (aliases As/Bs): qs[row][c], row-major stride 128
    float* qs = dyn;
#pragma unroll
    for (int i = 0; i < 8; i++) {
        float o[8];
#pragma unroll
        for (int jj = 0; jj < 4; jj++) unpack2(acc2[i][jj], o[2 * jj], o[2 * jj + 1]);
        float* p = qs + (mr + i) * 128 + nc;
        *(float4*)p = *(float4*)&o[0];
        *(float4*)(p + 4) = *(float4*)&o[4];
    }
    __syncthreads();

    // edge epilogue: one warp per edge
    int mend = (m0 + 128 < NN) ? m0 + 128 : NN;
    int beg = g_off[m0], end = g_off[mend];
    int lane = tid & 31, w = tid >> 5;
    for (int ei = beg + w; ei < end; ei += 8) {
        int e = g_elist[ei];
        int s = src[e];
        int d = dst[e];
        float4 ev = reinterpret_cast<const float4*>(g_eh + (size_t)e * EHD)[lane];
        float4 qv = reinterpret_cast<const float4*>(qs + (s - m0) * 128)[lane];
        float acc = ev.x * qv.x + ev.y * qv.y + ev.z * qv.z + ev.w * qv.w;
#pragma unroll
        for (int o = 16; o > 0; o >>= 1) acc += __shfl_xor_sync(0xffffffffu, acc, o);
        if (lane == 0) atomicAdd(&g_agg[d * 64 + kblk], acc + g_bb[s * 64 + kblk]);
    }
}

// ---------------- 5a: transpose GRU weights ----------------
__global__ void wt_kernel(const float* __restrict__ Wih, const float* __restrict__ Whh) {
    int i = blockIdx.x * blockDim.x + threadIdx.x;
    if (i < 192 * 64) {
        int j = i >> 6, h = i & 63;
        g_WihT[h * 192 + j] = Wih[i];
        g_WhhT[h * 192 + j] = Whh[i];
    }
}

// ---------------- 5: relu(agg) -> GRU -> LayerNorm ----------------
__global__ __launch_bounds__(256) void gru_ln_kernel(const float* __restrict__ hidden,
                                                     const float* __restrict__ bih,
                                                     const float* __restrict__ bhh,
                                                     const float* __restrict__ gamma,
                                                     const float* __restrict__ beta,
                                                     float* __restrict__ out) {
    __shared__ float xs[4][64], hs[4][64];
    __shared__ float redA[8], redB[8];
    int t = threadIdx.x;
    int sub = t >> 6, k = t & 63;
    int wid = t >> 5, lane = t & 31;
    float bi0 = bih[k], bi1 = bih[64 + k], bi2 = bih[128 + k];
    float bh0 = bhh[k], bh1 = bhh[64 + k], bh2 = bhh[128 + k];
    float gm = gamma[k], bt = beta[k];

    for (int n0 = blockIdx.x * 4; n0 < NN; n0 += gridDim.x * 4) {
        int n = n0 + sub;   // NN % 4 == 0
        float x = fmaxf(g_agg[n * 64 + k], 0.f);
        float hv = hidden[n * 64 + k];
        xs[sub][k] = x;
        hs[sub][k] = hv;
        __syncthreads();
        float gi0 = bi0, gi1 = bi1, gi2 = bi2;
        float gh0 = bh0, gh1 = bh1, gh2 = bh2;
#pragma unroll 8
        for (int h = 0; h < 64; h++) {
            float xv = xs[sub][h], hh = hs[sub][h];
            const float* wi = &g_WihT[h * 192];
            const float* wh = &g_WhhT[h * 192];
            gi0 = fmaf(xv, wi[k], gi0);
            gi1 = fmaf(xv, wi[64 + k], gi1);
            gi2 = fmaf(xv, wi[128 + k], gi2);
            gh0 = fmaf(hh, wh[k], gh0);
            gh1 = fmaf(hh, wh[64 + k], gh1);
            gh2 = fmaf(hh, wh[128 + k], gh2);
        }
        float r = 1.f / (1.f + expf(-(gi0 + gh0)));
        float z = 1.f / (1.f + expf(-(gi1 + gh1)));
        float nn2 = tanhf(gi2 + r * gh2);
        float o = (1.f - z) * nn2 + z * hv;

        float s1 = o, s2 = o * o;
#pragma unroll
        for (int d = 16; d > 0; d >>= 1) {
            s1 += __shfl_xor_sync(0xffffffffu, s1, d);
            s2 += __shfl_xor_sync(0xffffffffu, s2, d);
        }
        if (lane == 0) { redA[wid] = s1; redB[wid] = s2; }
        __syncthreads();
        float S1 = redA[sub * 2] + redA[sub * 2 + 1];
        float S2 = redB[sub * 2] + redB[sub * 2 + 1];
        float mu = S1 * 0.015625f;
        float var = S2 * 0.015625f - mu * mu;
        out[n * 64 + k] = (o - mu) * rsqrtf(var + 1e-5f) * gm + bt;
        __syncthreads();
    }
}

// ---------------- launch ----------------
extern "C" void kernel_launch(void* const* d_in, const int* in_sizes, int n_in,
                              void* d_out, int out_size) {
    const float* node   = (const float*)d_in[0];
    const float* edge   = (const float*)d_in[1];
    const float* hidden = (const float*)d_in[2];
    const int*   src    = (const int*)d_in[3];
    const int*   dst    = (const int*)d_in[4];
    const float* W1     = (const float*)d_in[5];
    const float* b1     = (const float*)d_in[6];
    const float* W2     = (const float*)d_in[7];
    const float* b2     = (const float*)d_in[8];
    const float* Wih    = (const float*)d_in[9];
    const float* Whh    = (const float*)d_in[10];
    const float* bih    = (const float*)d_in[11];
    const float* bhh    = (const float*)d_in[12];
    const float* gamma  = (const float*)d_in[13];
    const float* beta   = (const float*)d_in[14];
    float* out = (float*)d_out;

    static bool attr_set = false;
    if (!attr_set) {
        cudaFuncSetAttribute(eh_gemm, cudaFuncAttributeMaxDynamicSharedMemorySize, 65536);
        cudaFuncSetAttribute(fused_qmsg, cudaFuncAttributeMaxDynamicSharedMemorySize, 65536);
        attr_set = true;
    }

    zero_kernel<<<1024, 256>>>();
    wt_kernel<<<(192 * 64 + 255) / 256, 256>>>(Wih, Whh);
    bb_kernel<<<300, 256>>>(node, b2);
    eh_gemm<<<(NE + 127) / 128, 256, 65536>>>(edge, W1, b1);
    count_kernel<<<(NE + 255) / 256, 256>>>(src);
    scan_kernel<<<1, 1024>>>();
    scatter_kernel<<<(NE + 255) / 256, 256>>>(src);
    fused_qmsg<<<dim3(64, (NN + 127) / 128), 256, 65536>>>(node, W2, src, dst);
    gru_ln_kernel<<<296, 256>>>(hidden, bih, bhh, gamma, beta, out);
}

// round 3
// speedup vs baseline: 1.8504x; 1.8504x over previous
#include <cuda_runtime.h>
#include <math.h>

#define H 64
#define NN 12000
#define NE 50000
#define EHD 128          // 2H
#define QC 8192          // H * 2H  (columns of q)

// ---------------- scratch (device globals; allocation-free) ----------------
__device__ float g_eh[NE * EHD];          // 25.6 MB  relu(edge@W1.T+b1)
__device__ float g_q[NN * QC];            // 393 MB   q[n, k*128+c]
__device__ float g_agg[NN * H];           // 3 MB     scatter-sum target
__device__ float g_W1T[64 * 128];         // W1 transposed: [k][n]
__device__ float g_WihT[64 * 192];        // transposed GRU weights
__device__ float g_WhhT[64 * 192];
__device__ int   g_cnt[NN];
__device__ int   g_off[NN + 1];
__device__ int   g_cur[NN];
__device__ int   g_elist[NE];

// packed f32x2 helpers (bit-exact vs two fmaf)
__device__ __forceinline__ unsigned long long pack_dup(float a) {
    unsigned long long r;
    asm("mov.b64 %0, {%1, %1};" : "=l"(r) : "f"(a));
    return r;
}
__device__ __forceinline__ void fma2(unsigned long long& acc, unsigned long long a,
                                     unsigned long long b) {
    asm("fma.rn.f32x2 %0, %1, %2, %3;" : "=l"(acc) : "l"(a), "l"(b), "l"(acc));
}
__device__ __forceinline__ void unpack2(unsigned long long v, float& lo, float& hi) {
    asm("mov.b64 {%0, %1}, %2;" : "=f"(lo), "=f"(hi) : "l"(v));
}

// ---------------- 0: zero agg + counts ----------------
__global__ void zero_kernel() {
    int i = blockIdx.x * blockDim.x + threadIdx.x;
    int stride = gridDim.x * blockDim.x;
    for (int j = i; j < NN * H; j += stride) g_agg[j] = 0.f;
    for (int j = i; j < NN; j += stride) g_cnt[j] = 0;
}

// ---------------- 0b: transpose small weights ----------------
__global__ void wt_kernel(const float* __restrict__ Wih, const float* __restrict__ Whh,
                          const float* __restrict__ W1) {
    int i = blockIdx.x * blockDim.x + threadIdx.x;
    if (i < 192 * 64) {
        int j = i >> 6, h = i & 63;
        g_WihT[h * 192 + j] = Wih[i];
        g_WhhT[h * 192 + j] = Whh[i];
    }
    if (i < 128 * 64) {      // W1 is [128][64] row-major
        int n = i >> 6, k = i & 63;
        g_W1T[k * 128 + n] = W1[i];
    }
}

// ---------------- 1: eh = relu(edge @ W1.T + b1), tiled GEMM + FFMA2 --------
// M=NE, N=128, K=64. CTA tile 128x128. Static smem 48KB.
__global__ __launch_bounds__(256, 2) void eh_gemm(const float* __restrict__ edge,
                                                  const float* __restrict__ b1) {
    __shared__ float As[64 * 128];   // [k][m]
    __shared__ float Bs[32 * 128];   // [k][n] chunk
    int m0 = blockIdx.x * 128;
    int tid = threadIdx.x;

    for (int i = tid; i < 2048; i += 256) {
        int r = i >> 4, c4 = i & 15;
        float4 v = make_float4(0.f, 0.f, 0.f, 0.f);
        int m = m0 + r;
        if (m < NE) v = reinterpret_cast<const float4*>(edge)[m * 16 + c4];
        As[(c4 * 4 + 0) * 128 + r] = v.x;
        As[(c4 * 4 + 1) * 128 + r] = v.y;
        As[(c4 * 4 + 2) * 128 + r] = v.z;
        As[(c4 * 4 + 3) * 128 + r] = v.w;
    }

    int tx = tid & 15, ty = tid >> 4;
    int mr = ty * 8, nc = tx * 8;
    unsigned long long acc2[8][4];
#pragma unroll
    for (int i = 0; i < 8; i++)
#pragma unroll
        for (int jj = 0; jj < 4; jj++) acc2[i][jj] = 0ull;

    for (int kb = 0; kb < 64; kb += 32) {
        __syncthreads();
        for (int i = tid; i < 1024; i += 256)
            reinterpret_cast<float4*>(Bs)[i] =
                reinterpret_cast<const float4*>(g_W1T + kb * 128)[i];
        __syncthreads();
#pragma unroll 8
        for (int k = 0; k < 32; k++) {
            float a[8];
            *(float4*)&a[0] = *(const float4*)&As[(kb + k) * 128 + mr];
            *(float4*)&a[4] = *(const float4*)&As[(kb + k) * 128 + mr + 4];
            ulonglong2 b01 = *(const ulonglong2*)&Bs[k * 128 + nc];
            ulonglong2 b23 = *(const ulonglong2*)&Bs[k * 128 + nc + 4];
            unsigned long long bq[4] = {b01.x, b01.y, b23.x, b23.y};
#pragma unroll
            for (int i = 0; i < 8; i++) {
                unsigned long long ad = pack_dup(a[i]);
#pragma unroll
                for (int jj = 0; jj < 4; jj++) fma2(acc2[i][jj], ad, bq[jj]);
            }
        }
    }

    float bias[8];
#pragma unroll
    for (int j = 0; j < 8; j++) bias[j] = b1[nc + j];

#pragma unroll
    for (int i = 0; i < 8; i++) {
        int m = m0 + mr + i;
        if (m < NE) {
            float o[8];
#pragma unroll
            for (int jj = 0; jj < 4; jj++) unpack2(acc2[i][jj], o[2 * jj], o[2 * jj + 1]);
#pragma unroll
            for (int j = 0; j < 8; j++) o[j] = fmaxf(o[j] + bias[j], 0.f);
            float* dst = g_eh + (size_t)m * EHD + nc;
            *(float4*)dst = *(float4*)&o[0];
            *(float4*)(dst + 4) = *(float4*)&o[4];
        }
    }
}

// ---------------- 2: q GEMM with FFMA2 ----------------
// q[n, j] = sum_h node[n,h] * W2flat[h*8192 + j];  M=12000, N=8192, K=64.
__global__ __launch_bounds__(256, 2) void q_gemm(const float* __restrict__ node,
                                                 const float* __restrict__ W2) {
    __shared__ float As[64 * 128];   // [k][m]
    __shared__ float Bs[32 * 128];   // [k][n] chunk
    int m0 = blockIdx.y * 128, n0 = blockIdx.x * 128;
    int tid = threadIdx.x;

    for (int i = tid; i < 2048; i += 256) {
        int r = i >> 4, c4 = i & 15;
        float4 v = make_float4(0.f, 0.f, 0.f, 0.f);
        int m = m0 + r;
        if (m < NN) v = reinterpret_cast<const float4*>(node)[m * 16 + c4];
        As[(c4 * 4 + 0) * 128 + r] = v.x;
        As[(c4 * 4 + 1) * 128 + r] = v.y;
        As[(c4 * 4 + 2) * 128 + r] = v.z;
        As[(c4 * 4 + 3) * 128 + r] = v.w;
    }

    int tx = tid & 15, ty = tid >> 4;
    int mr = ty * 8, nc = tx * 8;
    unsigned long long acc2[8][4];
#pragma unroll
    for (int i = 0; i < 8; i++)
#pragma unroll
        for (int jj = 0; jj < 4; jj++) acc2[i][jj] = 0ull;

    for (int kb = 0; kb < 64; kb += 32) {
        __syncthreads();
        for (int i = tid; i < 1024; i += 256) {
            int r = i >> 5, c4 = i & 31;
            reinterpret_cast<float4*>(Bs)[r * 32 + c4] =
                reinterpret_cast<const float4*>(W2)[(kb + r) * 2048 + (n0 >> 2) + c4];
        }
        __syncthreads();
#pragma unroll 8
        for (int k = 0; k < 32; k++) {
            float a[8];
            *(float4*)&a[0] = *(const float4*)&As[(kb + k) * 128 + mr];
            *(float4*)&a[4] = *(const float4*)&As[(kb + k) * 128 + mr + 4];
            ulonglong2 b01 = *(const ulonglong2*)&Bs[k * 128 + nc];
            ulonglong2 b23 = *(const ulonglong2*)&Bs[k * 128 + nc + 4];
            unsigned long long bq[4] = {b01.x, b01.y, b23.x, b23.y};
#pragma unroll
            for (int i = 0; i < 8; i++) {
                unsigned long long ad = pack_dup(a[i]);
#pragma unroll
                for (int jj = 0; jj < 4; jj++) fma2(acc2[i][jj], ad, bq[jj]);
            }
        }
    }

#pragma unroll
    for (int i = 0; i < 8; i++) {
        int m = m0 + mr + i;
        if (m < NN) {
            float o[8];
#pragma unroll
            for (int jj = 0; jj < 4; jj++) unpack2(acc2[i][jj], o[2 * jj], o[2 * jj + 1]);
            float* dst = g_q + (size_t)m * QC + n0 + nc;
            *(float4*)dst = *(float4*)&o[0];
            *(float4*)(dst + 4) = *(float4*)&o[4];
        }
    }
}

// ---------------- 3: CSR by src ----------------
__global__ void count_kernel(const int* __restrict__ src) {
    int e = blockIdx.x * blockDim.x + threadIdx.x;
    if (e < NE) atomicAdd(&g_cnt[src[e]], 1);
}

__global__ void scan_kernel() {
    __shared__ int sm[1024];
    int tid = threadIdx.x;
    const int C = 12;   // 1024*12 >= NN
    int base = tid * C;
    int loc[C];
    int s = 0;
#pragma unroll
    for (int i = 0; i < C; i++) {
        int v = (base + i < NN) ? g_cnt[base + i] : 0;
        loc[i] = s;
        s += v;
    }
    sm[tid] = s;
    __syncthreads();
    for (int d = 1; d < 1024; d <<= 1) {
        int v = (tid >= d) ? sm[tid - d] : 0;
        __syncthreads();
        if (tid >= d) sm[tid] += v;
        __syncthreads();
    }
    int ex = sm[tid] - s;
#pragma unroll
    for (int i = 0; i < C; i++) {
        if (base + i < NN) {
            g_off[base + i] = ex + loc[i];
            g_cur[base + i] = ex + loc[i];
        }
    }
    if (tid == 1023) g_off[NN] = sm[1023];
}

__global__ void scatter_kernel(const int* __restrict__ src) {
    int e = blockIdx.x * blockDim.x + threadIdx.x;
    if (e < NE) {
        int p = atomicAdd(&g_cur[src[e]], 1);
        g_elist[p] = e;
    }
}

// ---------------- 4: per-src-node message + scatter-add ----------------
// msg[e,k] = sum_c eh[e,c]*q[src, k*128+c] + sum_h x[h]*b2[h*64+k]
__global__ __launch_bounds__(128) void msg_kernel(const float* __restrict__ node,
                                                  const float* __restrict__ b2,
                                                  const int* __restrict__ dst) {
    __shared__ float q_s[128 * 65];   // [c][k], stride 65 -> conflict-free
    __shared__ float eh_s[128];
    __shared__ float x_s[64];
    __shared__ float bb_s[64];
    __shared__ float part_s[128];
    int n = blockIdx.x;
    int t = threadIdx.x;

    int beg = g_off[n], end = g_off[n + 1];
    if (beg == end) return;   // uniform exit, no barriers crossed

    const float* qn = g_q + (size_t)n * QC;
#pragma unroll 8
    for (int j = t; j < QC; j += 128) {
        int k = j >> 7, c = j & 127;
        q_s[c * 65 + k] = qn[j];
    }
    if (t < 64) x_s[t] = node[n * 64 + t];
    __syncthreads();
    if (t < 64) {
        float bb = 0.f;
#pragma unroll 8
        for (int h = 0; h < 64; h++) bb = fmaf(x_s[h], b2[h * 64 + t], bb);
        bb_s[t] = bb;
    }

    int k = t & 63, half = t >> 6;
    const float* qp = q_s + (half * 64) * 65 + k;
    for (int ei = beg; ei < end; ei++) {
        int e = g_elist[ei];
        __syncthreads();
        eh_s[t] = g_eh[(size_t)e * EHD + t];
        __syncthreads();
        float acc = 0.f;
#pragma unroll 16
        for (int c = 0; c < 64; c++) acc = fmaf(eh_s[half * 64 + c], qp[c * 65], acc);
        part_s[t] = acc;
        __syncthreads();
        if (t < 64) {
            float m = part_s[t] + part_s[t + 64] + bb_s[t];
            atomicAdd(&g_agg[dst[e] * 64 + t], m);
        }
    }
}

// ---------------- 5: relu(agg) -> GRU -> LayerNorm ----------------
__global__ __launch_bounds__(256) void gru_ln_kernel(const float* __restrict__ hidden,
                                                     const float* __restrict__ bih,
                                                     const float* __restrict__ bhh,
                                                     const float* __restrict__ gamma,
                                                     const float* __restrict__ beta,
                                                     float* __restrict__ out) {
    __shared__ float xs[4][64], hs[4][64];
    __shared__ float redA[8], redB[8];
    int t = threadIdx.x;
    int sub = t >> 6, k = t & 63;
    int wid = t >> 5, lane = t & 31;
    float bi0 = bih[k], bi1 = bih[64 + k], bi2 = bih[128 + k];
    float bh0 = bhh[k], bh1 = bhh[64 + k], bh2 = bhh[128 + k];
    float gm = gamma[k], bt = beta[k];

    for (int n0 = blockIdx.x * 4; n0 < NN; n0 += gridDim.x * 4) {
        int n = n0 + sub;   // NN % 4 == 0
        float x = fmaxf(g_agg[n * 64 + k], 0.f);
        float hv = hidden[n * 64 + k];
        xs[sub][k] = x;
        hs[sub][k] = hv;
        __syncthreads();
        float gi0 = bi0, gi1 = bi1, gi2 = bi2;
        float gh0 = bh0, gh1 = bh1, gh2 = bh2;
#pragma unroll 8
        for (int h = 0; h < 64; h++) {
            float xv = xs[sub][h], hh = hs[sub][h];
            const float* wi = &g_WihT[h * 192];
            const float* wh = &g_WhhT[h * 192];
            gi0 = fmaf(xv, wi[k], gi0);
            gi1 = fmaf(xv, wi[64 + k], gi1);
            gi2 = fmaf(xv, wi[128 + k], gi2);
            gh0 = fmaf(hh, wh[k], gh0);
            gh1 = fmaf(hh, wh[64 + k], gh1);
            gh2 = fmaf(hh, wh[128 + k], gh2);
        }
        float r = 1.f / (1.f + expf(-(gi0 + gh0)));
        float z = 1.f / (1.f + expf(-(gi1 + gh1)));
        float nn2 = tanhf(gi2 + r * gh2);
        float o = (1.f - z) * nn2 + z * hv;

        float s1 = o, s2 = o * o;
#pragma unroll
        for (int d = 16; d > 0; d >>= 1) {
            s1 += __shfl_xor_sync(0xffffffffu, s1, d);
            s2 += __shfl_xor_sync(0xffffffffu, s2, d);
        }
        if (lane == 0) { redA[wid] = s1; redB[wid] = s2; }
        __syncthreads();
        float S1 = redA[sub * 2] + redA[sub * 2 + 1];
        float S2 = redB[sub * 2] + redB[sub * 2 + 1];
        float mu = S1 * 0.015625f;
        float var = S2 * 0.015625f - mu * mu;
        out[n * 64 + k] = (o - mu) * rsqrtf(var + 1e-5f) * gm + bt;
        __syncthreads();
    }
}

// ---------------- launch ----------------
extern "C" void kernel_launch(void* const* d_in, const int* in_sizes, int n_in,
                              void* d_out, int out_size) {
    const float* node   = (const float*)d_in[0];
    const float* edge   = (const float*)d_in[1];
    const float* hidden = (const float*)d_in[2];
    const int*   src    = (const int*)d_in[3];
    const int*   dst    = (const int*)d_in[4];
    const float* W1     = (const float*)d_in[5];
    const float* b1     = (const float*)d_in[6];
    const float* W2     = (const float*)d_in[7];
    const float* b2     = (const float*)d_in[8];
    const float* Wih    = (const float*)d_in[9];
    const float* Whh    = (const float*)d_in[10];
    const float* bih    = (const float*)d_in[11];
    const float* bhh    = (const float*)d_in[12];
    const float* gamma  = (const float*)d_in[13];
    const float* beta   = (const float*)d_in[14];
    float* out = (float*)d_out;

    zero_kernel<<<1024, 256>>>();
    wt_kernel<<<48, 256>>>(Wih, Whh, W1);
    eh_gemm<<<(NE + 127) / 128, 256>>>(edge, b1);
    count_kernel<<<(NE + 255) / 256, 256>>>(src);
    scan_kernel<<<1, 1024>>>();
    scatter_kernel<<<(NE + 255) / 256, 256>>>(src);
    q_gemm<<<dim3(QC / 128, (NN + 127) / 128), 256>>>(node, W2);
    msg_kernel<<<NN, 128>>>(node, b2, dst);
    gru_ln_kernel<<<296, 256>>>(hidden, bih, bhh, gamma, beta, out);
}

// round 5
// speedup vs baseline: 2.0090x; 1.0857x over previous
#include <cuda_runtime.h>
#include <cuda_bf16.h>
#include <math.h>
#include <cstdint>

#define H 64
#define NN 12000
#define NE 50000
#define EHD 128          // 2H
#define QC 8192          // H * 2H
#define NNP 12032        // NN padded to 128
#define KS 192           // split-K (hi|hi|lo)
#define STRQ 200         // smem row stride in bf16 (192 + 8 pad)

// ---------------- scratch (device globals; allocation-free) ----------------
__device__ __align__(16) float g_eh[NE * EHD];        // 25.6 MB
__device__ __align__(16) float g_q[(size_t)NN * QC];  // 393 MB
__device__ float g_agg[NN * H];
__device__ float g_W1T[64 * 128];
__device__ float g_WihT[64 * 192];
__device__ float g_WhhT[64 * 192];
__device__ __align__(16) __nv_bfloat16 g_Asplit[NNP * KS];   // node hi|hi|lo
__device__ __align__(16) __nv_bfloat16 g_Bsplit[QC * KS];    // W2^T hi|lo|hi
__device__ int g_cnt[NN];
__device__ int g_off[NN + 1];
__device__ int g_cur[NN];
__device__ int g_elist[NE];

__device__ __forceinline__ uint32_t smem_to_u32(const void* p) {
    uint32_t a;
    asm("{ .reg .u64 t; cvta.to.shared.u64 t, %1; cvt.u32.u64 %0, t; }" : "=r"(a) : "l"(p));
    return a;
}

// packed f32x2 helpers (bit-exact vs two fmaf)
__device__ __forceinline__ unsigned long long pack_dup(float a) {
    unsigned long long r;
    asm("mov.b64 %0, {%1, %1};" : "=l"(r) : "f"(a));
    return r;
}
__device__ __forceinline__ void fma2(unsigned long long& acc, unsigned long long a,
                                     unsigned long long b) {
    asm("fma.rn.f32x2 %0, %1, %2, %3;" : "=l"(acc) : "l"(a), "l"(b), "l"(acc));
}
__device__ __forceinline__ void unpack2(unsigned long long v, float& lo, float& hi) {
    asm("mov.b64 {%0, %1}, %2;" : "=f"(lo), "=f"(hi) : "l"(v));
}

// ---------------- 0: zero ----------------
__global__ void zero_kernel() {
    int i = blockIdx.x * blockDim.x + threadIdx.x;
    int stride = gridDim.x * blockDim.x;
    for (int j = i; j < NN * H; j += stride) g_agg[j] = 0.f;
    for (int j = i; j < NN; j += stride) g_cnt[j] = 0;
}

// ---------------- 0b: small-weight transposes ----------------
__global__ void wt_kernel(const float* __restrict__ Wih, const float* __restrict__ Whh,
                          const float* __restrict__ W1) {
    int i = blockIdx.x * blockDim.x + threadIdx.x;
    if (i < 192 * 64) {
        int j = i >> 6, h = i & 63;
        g_WihT[h * 192 + j] = Wih[i];
        g_WhhT[h * 192 + j] = Whh[i];
    }
    if (i < 128 * 64) {
        int n = i >> 6, k = i & 63;
        g_W1T[k * 128 + n] = W1[i];
    }
}

// ---------------- 0c: bf16 split of node (A) ----------------
__global__ void split_node(const float* __restrict__ node) {
    int i = blockIdx.x * blockDim.x + threadIdx.x;
    if (i < NNP * 64) {
        int n = i >> 6, h = i & 63;
        float x = (n < NN) ? node[n * 64 + h] : 0.f;
        __nv_bfloat16 hi = __float2bfloat16(x);
        __nv_bfloat16 lo = __float2bfloat16(x - __bfloat162float(hi));
        g_Asplit[n * KS + h] = hi;
        g_Asplit[n * KS + 64 + h] = hi;
        g_Asplit[n * KS + 128 + h] = lo;
    }
}

// ---------------- 0d: bf16 split + transpose of W2 (B) ----------------
// B[n][k] = W2flat[k*8192 + n], row layout: [hi(64) | lo(64) | hi(64)]
__global__ __launch_bounds__(256) void split_w2(const float* __restrict__ W2) {
    __shared__ float Ws[64 * 128];
    int n0 = blockIdx.x * 128;
    int t = threadIdx.x;
    for (int j = t; j < 8192; j += 256) {
        int k = j >> 7, n = j & 127;
        Ws[k * 128 + n] = W2[(size_t)k * QC + n0 + n];
    }
    __syncthreads();
    for (int j = t; j < 8192; j += 256) {
        int n = j >> 6, k = j & 63;
        float x = Ws[k * 128 + n];
        __nv_bfloat16 hi = __float2bfloat16(x);
        __nv_bfloat16 lo = __float2bfloat16(x - __bfloat162float(hi));
        size_t base = (size_t)(n0 + n) * KS;
        g_Bsplit[base + k] = hi;
        g_Bsplit[base + 64 + k] = lo;
        g_Bsplit[base + 128 + k] = hi;
    }
}

// ---------------- 1: eh = relu(edge @ W1.T + b1) ----------------
__global__ __launch_bounds__(256, 2) void eh_gemm(const float* __restrict__ edge,
                                                  const float* __restrict__ b1) {
    __shared__ float As[64 * 128];
    __shared__ float Bs[32 * 128];
    int m0 = blockIdx.x * 128;
    int tid = threadIdx.x;

    for (int i = tid; i < 2048; i += 256) {
        int r = i >> 4, c4 = i & 15;
        float4 v = make_float4(0.f, 0.f, 0.f, 0.f);
        int m = m0 + r;
        if (m < NE) v = reinterpret_cast<const float4*>(edge)[m * 16 + c4];
        As[(c4 * 4 + 0) * 128 + r] = v.x;
        As[(c4 * 4 + 1) * 128 + r] = v.y;
        As[(c4 * 4 + 2) * 128 + r] = v.z;
        As[(c4 * 4 + 3) * 128 + r] = v.w;
    }

    int tx = tid & 15, ty = tid >> 4;
    int mr = ty * 8, nc = tx * 8;
    unsigned long long acc2[8][4];
#pragma unroll
    for (int i = 0; i < 8; i++)
#pragma unroll
        for (int jj = 0; jj < 4; jj++) acc2[i][jj] = 0ull;

    for (int kb = 0; kb < 64; kb += 32) {
        __syncthreads();
        for (int i = tid; i < 1024; i += 256)
            reinterpret_cast<float4*>(Bs)[i] =
                reinterpret_cast<const float4*>(g_W1T + kb * 128)[i];
        __syncthreads();
#pragma unroll 8
        for (int k = 0; k < 32; k++) {
            float a[8];
            *(float4*)&a[0] = *(const float4*)&As[(kb + k) * 128 + mr];
            *(float4*)&a[4] = *(const float4*)&As[(kb + k) * 128 + mr + 4];
            ulonglong2 b01 = *(const ulonglong2*)&Bs[k * 128 + nc];
            ulonglong2 b23 = *(const ulonglong2*)&Bs[k * 128 + nc + 4];
            unsigned long long bq[4] = {b01.x, b01.y, b23.x, b23.y};
#pragma unroll
            for (int i = 0; i < 8; i++) {
                unsigned long long ad = pack_dup(a[i]);
#pragma unroll
                for (int jj = 0; jj < 4; jj++) fma2(acc2[i][jj], ad, bq[jj]);
            }
        }
    }

    float bias[8];
#pragma unroll
    for (int j = 0; j < 8; j++) bias[j] = b1[nc + j];

#pragma unroll
    for (int i = 0; i < 8; i++) {
        int m = m0 + mr + i;
        if (m < NE) {
            float o[8];
#pragma unroll
            for (int jj = 0; jj < 4; jj++) unpack2(acc2[i][jj], o[2 * jj], o[2 * jj + 1]);
#pragma unroll
            for (int j = 0; j < 8; j++) o[j] = fmaxf(o[j] + bias[j], 0.f);
            float* dst = g_eh + (size_t)m * EHD + nc;
            *(float4*)dst = *(float4*)&o[0];
            *(float4*)(dst + 4) = *(float4*)&o[4];
        }
    }
}

// ---------------- 2: q GEMM on mma.sync (bf16 split, K=192) ----------------
// CTA 128x128 tile, 8 warps of 32Mx64N. q = Asplit(128x192) @ Bsplit(128x192)^T
__global__ __launch_bounds__(256, 2) void q_mma() {
    extern __shared__ __nv_bfloat16 smq[];
    __nv_bfloat16* As = smq;               // [128][STRQ]
    __nv_bfloat16* Bs = smq + 128 * STRQ;  // [128][STRQ]
    int n0 = blockIdx.x * 128, m0 = blockIdx.y * 128;
    int tid = threadIdx.x;

    // stage A, B rows (192 bf16 = 24 x 16B chunks per row)
    for (int i = tid; i < 3072; i += 256) {
        int r = i / 24, c = i % 24;
        *reinterpret_cast<uint4*>(As + r * STRQ + c * 8) =
            reinterpret_cast<const uint4*>(g_Asplit + (size_t)(m0 + r) * KS)[c];
        *reinterpret_cast<uint4*>(Bs + r * STRQ + c * 8) =
            reinterpret_cast<const uint4*>(g_Bsplit + (size_t)(n0 + r) * KS)[c];
    }
    __syncthreads();

    int w = tid >> 5, lane = tid & 31;
    int wm = (w & 3) * 32, wn = (w >> 2) * 64;
    int g = lane >> 3;
    int arow = (lane & 7) + (g & 1) * 8, aka = (g >> 1) * 8;   // A ldmatrix lane addr
    int brow = (lane & 7) + (g >> 1) * 8, bka = (g & 1) * 8;   // B ldmatrix lane addr

    float acc[2][8][4];
#pragma unroll
    for (int im = 0; im < 2; im++)
#pragma unroll
        for (int jn = 0; jn < 8; jn++)
#pragma unroll
            for (int c = 0; c < 4; c++) acc[im][jn][c] = 0.f;

#pragma unroll
    for (int kk = 0; kk < 12; kk++) {
        int k0 = kk * 16;
        uint32_t a[2][4];
#pragma unroll
        for (int im = 0; im < 2; im++) {
            uint32_t addr = smem_to_u32(As + (wm + im * 16 + arow) * STRQ + k0 + aka);
            asm volatile("ldmatrix.sync.aligned.m8n8.x4.shared.b16 {%0,%1,%2,%3}, [%4];"
                         : "=r"(a[im][0]), "=r"(a[im][1]), "=r"(a[im][2]), "=r"(a[im][3])
                         : "r"(addr));
        }
        uint32_t b[4][4];
#pragma unroll
        for (int jb = 0; jb < 4; jb++) {
            uint32_t addr = smem_to_u32(Bs + (wn + jb * 16 + brow) * STRQ + k0 + bka);
            asm volatile("ldmatrix.sync.aligned.m8n8.x4.shared.b16 {%0,%1,%2,%3}, [%4];"
                         : "=r"(b[jb][0]), "=r"(b[jb][1]), "=r"(b[jb][2]), "=r"(b[jb][3])
                         : "r"(addr));
        }
#pragma unroll
        for (int im = 0; im < 2; im++)
#pragma unroll
            for (int jn = 0; jn < 8; jn++) {
                uint32_t b0 = b[jn >> 1][(jn & 1) * 2];
                uint32_t b1 = b[jn >> 1][(jn & 1) * 2 + 1];
                asm volatile(
                    "mma.sync.aligned.m16n8k16.row.col.f32.bf16.bf16.f32 "
                    "{%0,%1,%2,%3}, {%4,%5,%6,%7}, {%8,%9}, {%0,%1,%2,%3};"
                    : "+f"(acc[im][jn][0]), "+f"(acc[im][jn][1]),
                      "+f"(acc[im][jn][2]), "+f"(acc[im][jn][3])
                    : "r"(a[im][0]), "r"(a[im][1]), "r"(a[im][2]), "r"(a[im][3]),
                      "r"(b0), "r"(b1));
            }
    }

    // epilogue: c0,c1 at (row, col..col+1); c2,c3 at (row+8, ...)
#pragma unroll
    for (int im = 0; im < 2; im++) {
        int m = m0 + wm + im * 16 + (lane >> 2);
#pragma unroll
        for (int jn = 0; jn < 8; jn++) {
            int c = n0 + wn + jn * 8 + (lane & 3) * 2;
            if (m < NN)
                *reinterpret_cast<float2*>(&g_q[(size_t)m * QC + c]) =
                    make_float2(acc[im][jn][0], acc[im][jn][1]);
            if (m + 8 < NN)
                *reinterpret_cast<float2*>(&g_q[(size_t)(m + 8) * QC + c]) =
                    make_float2(acc[im][jn][2], acc[im][jn][3]);
        }
    }
}

// ---------------- 3: CSR by src ----------------
__global__ void count_kernel(const int* __restrict__ src) {
    int e = blockIdx.x * blockDim.x + threadIdx.x;
    if (e < NE) atomicAdd(&g_cnt[src[e]], 1);
}

__global__ void scan_kernel() {
    __shared__ int sm[1024];
    int tid = threadIdx.x;
    const int C = 12;
    int base = tid * C;
    int loc[C];
    int s = 0;
#pragma unroll
    for (int i = 0; i < C; i++) {
        int v = (base + i < NN) ? g_cnt[base + i] : 0;
        loc[i] = s;
        s += v;
    }
    sm[tid] = s;
    __syncthreads();
    for (int d = 1; d < 1024; d <<= 1) {
        int v = (tid >= d) ? sm[tid - d] : 0;
        __syncthreads();
        if (tid >= d) sm[tid] += v;
        __syncthreads();
    }
    int ex = sm[tid] - s;
#pragma unroll
    for (int i = 0; i < C; i++) {
        if (base + i < NN) {
            g_off[base + i] = ex + loc[i];
            g_cur[base + i] = ex + loc[i];
        }
    }
    if (tid == 1023) g_off[NN] = sm[1023];
}

__global__ void scatter_kernel(const int* __restrict__ src) {
    int e = blockIdx.x * blockDim.x + threadIdx.x;
    if (e < NE) {
        int p = atomicAdd(&g_cur[src[e]], 1);
        g_elist[p] = e;
    }
}

// ---------------- 4: per-src-node message + scatter-add ----------------
// thread t: k = t>>1, half = t&1; no per-edge barriers; eh read from gmem
__global__ __launch_bounds__(128) void msg_kernel(const float* __restrict__ node,
                                                  const float* __restrict__ b2,
                                                  const int* __restrict__ dst) {
    __shared__ float q_s[64 * 132];   // [k][c] rows padded to 132 floats
    __shared__ float x_s[64];
    __shared__ float bb_s[64];
    int n = blockIdx.x;
    int t = threadIdx.x;

    int beg = g_off[n], end = g_off[n + 1];
    if (beg == end) return;

    const float4* qn = reinterpret_cast<const float4*>(g_q + (size_t)n * QC);
#pragma unroll 4
    for (int j = t; j < 2048; j += 128) {
        int k = j >> 5, c4 = j & 31;
        *reinterpret_cast<float4*>(&q_s[k * 132 + c4 * 4]) = qn[j];
    }
    if (t < 64) x_s[t] = node[n * 64 + t];
    __syncthreads();
    if (t < 64) {
        float bb = 0.f;
#pragma unroll 8
        for (int h = 0; h < 64; h++) bb = fmaf(x_s[h], b2[h * 64 + t], bb);
        bb_s[t] = bb;
    }
    __syncthreads();

    int k = t >> 1, half = t & 1;
    const float4* qk = reinterpret_cast<const float4*>(&q_s[k * 132 + half * 64]);
    for (int ei = beg; ei < end; ei++) {
        int e = g_elist[ei];
        const float4* ep = reinterpret_cast<const float4*>(g_eh + (size_t)e * EHD) + half * 16;
        float acc = 0.f;
#pragma unroll
        for (int g = 0; g < 16; g++) {
            float4 ev = ep[g];
            float4 qv = qk[g];
            acc += ev.x * qv.x + ev.y * qv.y + ev.z * qv.z + ev.w * qv.w;
        }
        acc += __shfl_xor_sync(0xffffffffu, acc, 1);
        if (half == 0) {
            int d = dst[e];
            atomicAdd(&g_agg[d * 64 + k], acc + bb_s[k]);
        }
    }
}

// ---------------- 5: relu(agg) -> GRU -> LayerNorm ----------------
__global__ __launch_bounds__(256) void gru_ln_kernel(const float* __restrict__ hidden,
                                                     const float* __restrict__ bih,
                                                     const float* __restrict__ bhh,
                                                     const float* __restrict__ gamma,
                                                     const float* __restrict__ beta,
                                                     float* __restrict__ out) {
    __shared__ float xs[4][64], hs[4][64];
    __shared__ float redA[8], redB[8];
    int t = threadIdx.x;
    int sub = t >> 6, k = t & 63;
    int wid = t >> 5, lane = t & 31;
    float bi0 = bih[k], bi1 = bih[64 + k], bi2 = bih[128 + k];
    float bh0 = bhh[k], bh1 = bhh[64 + k], bh2 = bhh[128 + k];
    float gm = gamma[k], bt = beta[k];

    for (int n0 = blockIdx.x * 4; n0 < NN; n0 += gridDim.x * 4) {
        int n = n0 + sub;
        float x = fmaxf(g_agg[n * 64 + k], 0.f);
        float hv = hidden[n * 64 + k];
        xs[sub][k] = x;
        hs[sub][k] = hv;
        __syncthreads();
        float gi0 = bi0, gi1 = bi1, gi2 = bi2;
        float gh0 = bh0, gh1 = bh1, gh2 = bh2;
#pragma unroll 8
        for (int h = 0; h < 64; h++) {
            float xv = xs[sub][h], hh = hs[sub][h];
            const float* wi = &g_WihT[h * 192];
            const float* wh = &g_WhhT[h * 192];
            gi0 = fmaf(xv, wi[k], gi0);
            gi1 = fmaf(xv, wi[64 + k], gi1);
            gi2 = fmaf(xv, wi[128 + k], gi2);
            gh0 = fmaf(hh, wh[k], gh0);
            gh1 = fmaf(hh, wh[64 + k], gh1);
            gh2 = fmaf(hh, wh[128 + k], gh2);
        }
        float r = 1.f / (1.f + expf(-(gi0 + gh0)));
        float z = 1.f / (1.f + expf(-(gi1 + gh1)));
        float nn2 = tanhf(gi2 + r * gh2);
        float o = (1.f - z) * nn2 + z * hv;

        float s1 = o, s2 = o * o;
#pragma unroll
        for (int d = 16; d > 0; d >>= 1) {
            s1 += __shfl_xor_sync(0xffffffffu, s1, d);
            s2 += __shfl_xor_sync(0xffffffffu, s2, d);
        }
        if (lane == 0) { redA[wid] = s1; redB[wid] = s2; }
        __syncthreads();
        float S1 = redA[sub * 2] + redA[sub * 2 + 1];
        float S2 = redB[sub * 2] + redB[sub * 2 + 1];
        float mu = S1 * 0.015625f;
        float var = S2 * 0.015625f - mu * mu;
        out[n * 64 + k] = (o - mu) * rsqrtf(var + 1e-5f) * gm + bt;
        __syncthreads();
    }
}

// ---------------- launch ----------------
extern "C" void kernel_launch(void* const* d_in, const int* in_sizes, int n_in,
                              void* d_out, int out_size) {
    const float* node   = (const float*)d_in[0];
    const float* edge   = (const float*)d_in[1];
    const float* hidden = (const float*)d_in[2];
    const int*   src    = (const int*)d_in[3];
    const int*   dst    = (const int*)d_in[4];
    const float* W1     = (const float*)d_in[5];
    const float* b1     = (const float*)d_in[6];
    const float* W2     = (const float*)d_in[7];
    const float* b2     = (const float*)d_in[8];
    const float* Wih    = (const float*)d_in[9];
    const float* Whh    = (const float*)d_in[10];
    const float* bih    = (const float*)d_in[11];
    const float* bhh    = (const float*)d_in[12];
    const float* gamma  = (const float*)d_in[13];
    const float* beta   = (const float*)d_in[14];
    float* out = (float*)d_out;

    const int QSMEM = 2 * 128 * STRQ * 2;   // 102400 B
    cudaFuncSetAttribute(q_mma, cudaFuncAttributeMaxDynamicSharedMemorySize, QSMEM);

    zero_kernel<<<1024, 256>>>();
    wt_kernel<<<48, 256>>>(Wih, Whh, W1);
    split_node<<<(NNP * 64 + 255) / 256, 256>>>(node);
    split_w2<<<64, 256>>>(W2);
    eh_gemm<<<(NE + 127) / 128, 256>>>(edge, b1);
    count_kernel<<<(NE + 255) / 256, 256>>>(src);
    scan_kernel<<<1, 1024>>>();
    scatter_kernel<<<(NE + 255) / 256, 256>>>(src);
    q_mma<<<dim3(QC / 128, NNP / 128), 256, QSMEM>>>();
    msg_kernel<<<NN, 128>>>(node, b2, dst);
    gru_ln_kernel<<<296, 256>>>(hidden, bih, bhh, gamma, beta, out);
}

// round 6
// speedup vs baseline: 2.1424x; 1.0664x over previous
#include <cuda_runtime.h>
#include <cuda_bf16.h>
#include <math.h>
#include <cstdint>

#define H 64
#define NN 12000
#define NE 50000
#define EHD 128          // 2H
#define QC 8192          // H * 2H
#define NNP 12032        // NN padded to 128
#define NEP 50048        // NE padded to 128
#define KS 192           // split-K (hi|hi|lo)
#define STRQ 200         // smem row stride (bf16) for eh_mma
#define STR2 72          // smem row stride (bf16) for q_mma chunks

// ---------------- scratch (device globals; allocation-free) ----------------
__device__ __align__(16) float g_eh[NE * EHD];        // 25.6 MB
__device__ __align__(16) float g_q[(size_t)NN * QC];  // 393 MB
__device__ float g_agg[NN * H];
__device__ float g_WihT[64 * 192];
__device__ float g_WhhT[64 * 192];
__device__ __align__(16) __nv_bfloat16 g_Asplit[NNP * KS];   // node  hi|hi|lo
__device__ __align__(16) __nv_bfloat16 g_Bsplit[QC * KS];    // W2^T  hi|lo|hi
__device__ __align__(16) __nv_bfloat16 g_Esplit[NEP * KS];   // edge  hi|hi|lo
__device__ __align__(16) __nv_bfloat16 g_W1split[128 * KS];  // W1    hi|lo|hi
__device__ int g_cnt[NN];
__device__ int g_off[NN + 1];
__device__ int g_cur[NN];
__device__ int g_elist[NE];

__device__ __forceinline__ uint32_t smem_to_u32(const void* p) {
    uint32_t a;
    asm("{ .reg .u64 t; cvta.to.shared.u64 t, %1; cvt.u32.u64 %0, t; }" : "=r"(a) : "l"(p));
    return a;
}
__device__ __forceinline__ void cp16(void* s, const void* g) {
    uint32_t sa = smem_to_u32(s);
    asm volatile("cp.async.cg.shared.global [%0], [%1], 16;" :: "r"(sa), "l"(g));
}

// ---------------- 0: zero ----------------
__global__ void zero_kernel() {
    int i = blockIdx.x * blockDim.x + threadIdx.x;
    int stride = gridDim.x * blockDim.x;
    for (int j = i; j < NN * H; j += stride) g_agg[j] = 0.f;
    for (int j = i; j < NN; j += stride) g_cnt[j] = 0;
}

// ---------------- 0b: small-weight transposes + W1 split ----------------
__global__ void wt_kernel(const float* __restrict__ Wih, const float* __restrict__ Whh,
                          const float* __restrict__ W1) {
    int i = blockIdx.x * blockDim.x + threadIdx.x;
    if (i < 192 * 64) {
        int j = i >> 6, h = i & 63;
        g_WihT[h * 192 + j] = Wih[i];
        g_WhhT[h * 192 + j] = Whh[i];
    }
    if (i < 128 * 64) {
        int n = i >> 6, k = i & 63;
        float x = W1[i];
        __nv_bfloat16 hi = __float2bfloat16(x);
        __nv_bfloat16 lo = __float2bfloat16(x - __bfloat162float(hi));
        g_W1split[n * KS + k] = hi;
        g_W1split[n * KS + 64 + k] = lo;
        g_W1split[n * KS + 128 + k] = hi;
    }
}

// ---------------- 0c: bf16 split of node (A side: hi|hi|lo) ----------------
__global__ void split_node(const float* __restrict__ node) {
    int i = blockIdx.x * blockDim.x + threadIdx.x;
    if (i < NNP * 64) {
        int n = i >> 6, h = i & 63;
        float x = (n < NN) ? node[n * 64 + h] : 0.f;
        __nv_bfloat16 hi = __float2bfloat16(x);
        __nv_bfloat16 lo = __float2bfloat16(x - __bfloat162float(hi));
        g_Asplit[n * KS + h] = hi;
        g_Asplit[n * KS + 64 + h] = hi;
        g_Asplit[n * KS + 128 + h] = lo;
    }
}

// ---------------- 0d: bf16 split + transpose of W2 (B side: hi|lo|hi) -------
__global__ __launch_bounds__(256) void split_w2(const float* __restrict__ W2) {
    __shared__ float Ws[64 * 128];
    int n0 = blockIdx.x * 128;
    int t = threadIdx.x;
    for (int j = t; j < 8192; j += 256) {
        int k = j >> 7, n = j & 127;
        Ws[k * 128 + n] = W2[(size_t)k * QC + n0 + n];
    }
    __syncthreads();
    for (int j = t; j < 8192; j += 256) {
        int n = j >> 6, k = j & 63;
        float x = Ws[k * 128 + n];
        __nv_bfloat16 hi = __float2bfloat16(x);
        __nv_bfloat16 lo = __float2bfloat16(x - __bfloat162float(hi));
        size_t base = (size_t)(n0 + n) * KS;
        g_Bsplit[base + k] = hi;
        g_Bsplit[base + 64 + k] = lo;
        g_Bsplit[base + 128 + k] = hi;
    }
}

// ---------------- 0e: bf16 split of edge (A side: hi|hi|lo) ----------------
__global__ void split_edge(const float* __restrict__ edge) {
    int i = blockIdx.x * blockDim.x + threadIdx.x;
    if (i < NEP * 64) {
        int n = i >> 6, h = i & 63;
        float x = (n < NE) ? edge[n * 64 + h] : 0.f;
        __nv_bfloat16 hi = __float2bfloat16(x);
        __nv_bfloat16 lo = __float2bfloat16(x - __bfloat162float(hi));
        g_Esplit[n * KS + h] = hi;
        g_Esplit[n * KS + 64 + h] = hi;
        g_Esplit[n * KS + 128 + h] = lo;
    }
}

// ---------------- 2: q GEMM on mma.sync, cp.async pipelined ----------------
// CTA 128x128 tile, 8 warps of 32Mx64N, K=192 in 3 chunks of 64 (double buffer)
__global__ __launch_bounds__(256) void q_mma() {
    extern __shared__ __nv_bfloat16 smq[];
    __nv_bfloat16* As = smq;               // [2][128][STR2]
    __nv_bfloat16* Bs = smq + 2 * 128 * STR2;
    int n0 = blockIdx.x * 128, m0 = blockIdx.y * 128;
    int tid = threadIdx.x;

    int w = tid >> 5, lane = tid & 31;
    int wm = (w & 3) * 32, wn = (w >> 2) * 64;
    int g = lane >> 3;
    int arow = (lane & 7) + (g & 1) * 8, aka = (g >> 1) * 8;
    int brow = (lane & 7) + (g >> 1) * 8, bka = (g & 1) * 8;

    float acc[2][8][4];
#pragma unroll
    for (int im = 0; im < 2; im++)
#pragma unroll
        for (int jn = 0; jn < 8; jn++)
#pragma unroll
            for (int c = 0; c < 4; c++) acc[im][jn][c] = 0.f;

    // stage chunk c (64 k-cols) into buffer c&1
#define STAGE(c) do { \
        int _buf = (c) & 1; \
        __nv_bfloat16* _Ad = As + _buf * 128 * STR2; \
        __nv_bfloat16* _Bd = Bs + _buf * 128 * STR2; \
        const __nv_bfloat16* _Ag = g_Asplit + (size_t)m0 * KS + (c) * 64; \
        const __nv_bfloat16* _Bg = g_Bsplit + (size_t)n0 * KS + (c) * 64; \
        _Pragma("unroll") \
        for (int _i = 0; _i < 4; _i++) { \
            int _idx = tid + _i * 256; \
            int _r = _idx >> 3, _j = _idx & 7; \
            cp16(_Ad + _r * STR2 + _j * 8, _Ag + (size_t)_r * KS + _j * 8); \
            cp16(_Bd + _r * STR2 + _j * 8, _Bg + (size_t)_r * KS + _j * 8); \
        } \
        asm volatile("cp.async.commit_group;"); \
    } while (0)

    STAGE(0);
#pragma unroll
    for (int c = 0; c < 3; c++) {
        if (c + 1 < 3) STAGE(c + 1);
        if (c + 1 < 3) asm volatile("cp.async.wait_group 1;");
        else           asm volatile("cp.async.wait_group 0;");
        __syncthreads();
        const __nv_bfloat16* Ab = As + (c & 1) * 128 * STR2;
        const __nv_bfloat16* Bb = Bs + (c & 1) * 128 * STR2;
#pragma unroll
        for (int ks = 0; ks < 4; ks++) {
            int k0 = ks * 16;
            uint32_t a[2][4];
#pragma unroll
            for (int im = 0; im < 2; im++) {
                uint32_t addr = smem_to_u32(Ab + (wm + im * 16 + arow) * STR2 + k0 + aka);
                asm volatile("ldmatrix.sync.aligned.m8n8.x4.shared.b16 {%0,%1,%2,%3}, [%4];"
                             : "=r"(a[im][0]), "=r"(a[im][1]), "=r"(a[im][2]), "=r"(a[im][3])
                             : "r"(addr));
            }
            uint32_t b[4][4];
#pragma unroll
            for (int jb = 0; jb < 4; jb++) {
                uint32_t addr = smem_to_u32(Bb + (wn + jb * 16 + brow) * STR2 + k0 + bka);
                asm volatile("ldmatrix.sync.aligned.m8n8.x4.shared.b16 {%0,%1,%2,%3}, [%4];"
                             : "=r"(b[jb][0]), "=r"(b[jb][1]), "=r"(b[jb][2]), "=r"(b[jb][3])
                             : "r"(addr));
            }
#pragma unroll
            for (int im = 0; im < 2; im++)
#pragma unroll
                for (int jn = 0; jn < 8; jn++) {
                    uint32_t b0 = b[jn >> 1][(jn & 1) * 2];
                    uint32_t b1 = b[jn >> 1][(jn & 1) * 2 + 1];
                    asm volatile(
                        "mma.sync.aligned.m16n8k16.row.col.f32.bf16.bf16.f32 "
                        "{%0,%1,%2,%3}, {%4,%5,%6,%7}, {%8,%9}, {%0,%1,%2,%3};"
                        : "+f"(acc[im][jn][0]), "+f"(acc[im][jn][1]),
                          "+f"(acc[im][jn][2]), "+f"(acc[im][jn][3])
                        : "r"(a[im][0]), "r"(a[im][1]), "r"(a[im][2]), "r"(a[im][3]),
                          "r"(b0), "r"(b1));
                }
        }
        __syncthreads();
    }
#undef STAGE

#pragma unroll
    for (int im = 0; im < 2; im++) {
        int m = m0 + wm + im * 16 + (lane >> 2);
#pragma unroll
        for (int jn = 0; jn < 8; jn++) {
            int c = n0 + wn + jn * 8 + (lane & 3) * 2;
            if (m < NN)
                *reinterpret_cast<float2*>(&g_q[(size_t)m * QC + c]) =
                    make_float2(acc[im][jn][0], acc[im][jn][1]);
            if (m + 8 < NN)
                *reinterpret_cast<float2*>(&g_q[(size_t)(m + 8) * QC + c]) =
                    make_float2(acc[im][jn][2], acc[im][jn][3]);
        }
    }
}

// ---------------- 1: eh = relu(edge @ W1.T + b1) on mma.sync ----------------
// M=NEP, N=128, K=192; single n-block; non-pipelined (small B)
__global__ __launch_bounds__(256, 2) void eh_mma(const float* __restrict__ b1) {
    extern __shared__ __nv_bfloat16 sme[];
    __nv_bfloat16* As = sme;               // [128][STRQ]
    __nv_bfloat16* Bs = sme + 128 * STRQ;  // [128][STRQ]
    int m0 = blockIdx.x * 128;
    int tid = threadIdx.x;

    for (int i = tid; i < 3072; i += 256) {
        int r = i / 24, c = i % 24;
        *reinterpret_cast<uint4*>(As + r * STRQ + c * 8) =
            reinterpret_cast<const uint4*>(g_Esplit + (size_t)(m0 + r) * KS)[c];
        *reinterpret_cast<uint4*>(Bs + r * STRQ + c * 8) =
            reinterpret_cast<const uint4*>(g_W1split + (size_t)r * KS)[c];
    }
    __syncthreads();

    int w = tid >> 5, lane = tid & 31;
    int wm = (w & 3) * 32, wn = (w >> 2) * 64;
    int g = lane >> 3;
    int arow = (lane & 7) + (g & 1) * 8, aka = (g >> 1) * 8;
    int brow = (lane & 7) + (g >> 1) * 8, bka = (g & 1) * 8;

    float acc[2][8][4];
#pragma unroll
    for (int im = 0; im < 2; im++)
#pragma unroll
        for (int jn = 0; jn < 8; jn++)
#pragma unroll
            for (int c = 0; c < 4; c++) acc[im][jn][c] = 0.f;

#pragma unroll
    for (int kk = 0; kk < 12; kk++) {
        int k0 = kk * 16;
        uint32_t a[2][4];
#pragma unroll
        for (int im = 0; im < 2; im++) {
            uint32_t addr = smem_to_u32(As + (wm + im * 16 + arow) * STRQ + k0 + aka);
            asm volatile("ldmatrix.sync.aligned.m8n8.x4.shared.b16 {%0,%1,%2,%3}, [%4];"
                         : "=r"(a[im][0]), "=r"(a[im][1]), "=r"(a[im][2]), "=r"(a[im][3])
                         : "r"(addr));
        }
        uint32_t b[4][4];
#pragma unroll
        for (int jb = 0; jb < 4; jb++) {
            uint32_t addr = smem_to_u32(Bs + (wn + jb * 16 + brow) * STRQ + k0 + bka);
            asm volatile("ldmatrix.sync.aligned.m8n8.x4.shared.b16 {%0,%1,%2,%3}, [%4];"
                         : "=r"(b[jb][0]), "=r"(b[jb][1]), "=r"(b[jb][2]), "=r"(b[jb][3])
                         : "r"(addr));
        }
#pragma unroll
        for (int im = 0; im < 2; im++)
#pragma unroll
            for (int jn = 0; jn < 8; jn++) {
                uint32_t b0 = b[jn >> 1][(jn & 1) * 2];
                uint32_t b1 = b[jn >> 1][(jn & 1) * 2 + 1];
                asm volatile(
                    "mma.sync.aligned.m16n8k16.row.col.f32.bf16.bf16.f32 "
                    "{%0,%1,%2,%3}, {%4,%5,%6,%7}, {%8,%9}, {%0,%1,%2,%3};"
                    : "+f"(acc[im][jn][0]), "+f"(acc[im][jn][1]),
                      "+f"(acc[im][jn][2]), "+f"(acc[im][jn][3])
                    : "r"(a[im][0]), "r"(a[im][1]), "r"(a[im][2]), "r"(a[im][3]),
                      "r"(b0), "r"(b1));
            }
    }

#pragma unroll
    for (int im = 0; im < 2; im++) {
        int m = m0 + wm + im * 16 + (lane >> 2);
#pragma unroll
        for (int jn = 0; jn < 8; jn++) {
            int c = wn + jn * 8 + (lane & 3) * 2;
            float bb0 = b1[c], bb1 = b1[c + 1];
            if (m < NE)
                *reinterpret_cast<float2*>(&g_eh[(size_t)m * EHD + c]) =
                    make_float2(fmaxf(acc[im][jn][0] + bb0, 0.f),
                                fmaxf(acc[im][jn][1] + bb1, 0.f));
            if (m + 8 < NE)
                *reinterpret_cast<float2*>(&g_eh[(size_t)(m + 8) * EHD + c]) =
                    make_float2(fmaxf(acc[im][jn][2] + bb0, 0.f),
                                fmaxf(acc[im][jn][3] + bb1, 0.f));
        }
    }
}

// ---------------- 3: CSR by src ----------------
__global__ void count_kernel(const int* __restrict__ src) {
    int e = blockIdx.x * blockDim.x + threadIdx.x;
    if (e < NE) atomicAdd(&g_cnt[src[e]], 1);
}

__global__ void scan_kernel() {
    __shared__ int sm[1024];
    int tid = threadIdx.x;
    const int C = 12;
    int base = tid * C;
    int loc[C];
    int s = 0;
#pragma unroll
    for (int i = 0; i < C; i++) {
        int v = (base + i < NN) ? g_cnt[base + i] : 0;
        loc[i] = s;
        s += v;
    }
    sm[tid] = s;
    __syncthreads();
    for (int d = 1; d < 1024; d <<= 1) {
        int v = (tid >= d) ? sm[tid - d] : 0;
        __syncthreads();
        if (tid >= d) sm[tid] += v;
        __syncthreads();
    }
    int ex = sm[tid] - s;
#pragma unroll
    for (int i = 0; i < C; i++) {
        if (base + i < NN) {
            g_off[base + i] = ex + loc[i];
            g_cur[base + i] = ex + loc[i];
        }
    }
    if (tid == 1023) g_off[NN] = sm[1023];
}

__global__ void scatter_kernel(const int* __restrict__ src) {
    int e = blockIdx.x * blockDim.x + threadIdx.x;
    if (e < NE) {
        int p = atomicAdd(&g_cur[src[e]], 1);
        g_elist[p] = e;
    }
}

// ---------------- 4: per-src-node message + scatter-add ----------------
__global__ __launch_bounds__(128) void msg_kernel(const float* __restrict__ node,
                                                  const float* __restrict__ b2,
                                                  const int* __restrict__ dst) {
    __shared__ float q_s[64 * 132];
    __shared__ float x_s[64];
    __shared__ float bb_s[64];
    int n = blockIdx.x;
    int t = threadIdx.x;

    int beg = g_off[n], end = g_off[n + 1];
    if (beg == end) return;

    const float4* qn = reinterpret_cast<const float4*>(g_q + (size_t)n * QC);
#pragma unroll 4
    for (int j = t; j < 2048; j += 128) {
        int k = j >> 5, c4 = j & 31;
        *reinterpret_cast<float4*>(&q_s[k * 132 + c4 * 4]) = qn[j];
    }
    if (t < 64) x_s[t] = node[n * 64 + t];
    __syncthreads();
    if (t < 64) {
        float bb = 0.f;
#pragma unroll 8
        for (int h = 0; h < 64; h++) bb = fmaf(x_s[h], b2[h * 64 + t], bb);
        bb_s[t] = bb;
    }
    __syncthreads();

    int k = t >> 1, half = t & 1;
    const float4* qk = reinterpret_cast<const float4*>(&q_s[k * 132 + half * 64]);
    for (int ei = beg; ei < end; ei++) {
        int e = g_elist[ei];
        const float4* ep = reinterpret_cast<const float4*>(g_eh + (size_t)e * EHD) + half * 16;
        float acc = 0.f;
#pragma unroll
        for (int g = 0; g < 16; g++) {
            float4 ev = ep[g];
            float4 qv = qk[g];
            acc += ev.x * qv.x + ev.y * qv.y + ev.z * qv.z + ev.w * qv.w;
        }
        acc += __shfl_xor_sync(0xffffffffu, acc, 1);
        if (half == 0) {
            int d = dst[e];
            atomicAdd(&g_agg[d * 64 + k], acc + bb_s[k]);
        }
    }
}

// ---------------- 5: relu(agg) -> GRU -> LayerNorm ----------------
__global__ __launch_bounds__(256) void gru_ln_kernel(const float* __restrict__ hidden,
                                                     const float* __restrict__ bih,
                                                     const float* __restrict__ bhh,
                                                     const float* __restrict__ gamma,
                                                     const float* __restrict__ beta,
                                                     float* __restrict__ out) {
    __shared__ float xs[4][64], hs[4][64];
    __shared__ float redA[8], redB[8];
    int t = threadIdx.x;
    int sub = t >> 6, k = t & 63;
    int wid = t >> 5, lane = t & 31;
    float bi0 = bih[k], bi1 = bih[64 + k], bi2 = bih[128 + k];
    float bh0 = bhh[k], bh1 = bhh[64 + k], bh2 = bhh[128 + k];
    float gm = gamma[k], bt = beta[k];

    for (int n0 = blockIdx.x * 4; n0 < NN; n0 += gridDim.x * 4) {
        int n = n0 + sub;
        float x = fmaxf(g_agg[n * 64 + k], 0.f);
        float hv = hidden[n * 64 + k];
        xs[sub][k] = x;
        hs[sub][k] = hv;
        __syncthreads();
        float gi0 = bi0, gi1 = bi1, gi2 = bi2;
        float gh0 = bh0, gh1 = bh1, gh2 = bh2;
#pragma unroll 8
        for (int h = 0; h < 64; h++) {
            float xv = xs[sub][h], hh = hs[sub][h];
            const float* wi = &g_WihT[h * 192];
            const float* wh = &g_WhhT[h * 192];
            gi0 = fmaf(xv, wi[k], gi0);
            gi1 = fmaf(xv, wi[64 + k], gi1);
            gi2 = fmaf(xv, wi[128 + k], gi2);
            gh0 = fmaf(hh, wh[k], gh0);
            gh1 = fmaf(hh, wh[64 + k], gh1);
            gh2 = fmaf(hh, wh[128 + k], gh2);
        }
        float r = 1.f / (1.f + expf(-(gi0 + gh0)));
        float z = 1.f / (1.f + expf(-(gi1 + gh1)));
        float nn2 = tanhf(gi2 + r * gh2);
        float o = (1.f - z) * nn2 + z * hv;

        float s1 = o, s2 = o * o;
#pragma unroll
        for (int d = 16; d > 0; d >>= 1) {
            s1 += __shfl_xor_sync(0xffffffffu, s1, d);
            s2 += __shfl_xor_sync(0xffffffffu, s2, d);
        }
        if (lane == 0) { redA[wid] = s1; redB[wid] = s2; }
        __syncthreads();
        float S1 = redA[sub * 2] + redA[sub * 2 + 1];
        float S2 = redB[sub * 2] + redB[sub * 2 + 1];
        float mu = S1 * 0.015625f;
        float var = S2 * 0.015625f - mu * mu;
        out[n * 64 + k] = (o - mu) * rsqrtf(var + 1e-5f) * gm + bt;
        __syncthreads();
    }
}

// ---------------- launch ----------------
extern "C" void kernel_launch(void* const* d_in, const int* in_sizes, int n_in,
                              void* d_out, int out_size) {
    const float* node   = (const float*)d_in[0];
    const float* edge   = (const float*)d_in[1];
    const float* hidden = (const float*)d_in[2];
    const int*   src    = (const int*)d_in[3];
    const int*   dst    = (const int*)d_in[4];
    const float* W1     = (const float*)d_in[5];
    const float* b1     = (const float*)d_in[6];
    const float* W2     = (const float*)d_in[7];
    const float* b2     = (const float*)d_in[8];
    const float* Wih    = (const float*)d_in[9];
    const float* Whh    = (const float*)d_in[10];
    const float* bih    = (const float*)d_in[11];
    const float* bhh    = (const float*)d_in[12];
    const float* gamma  = (const float*)d_in[13];
    const float* beta   = (const float*)d_in[14];
    float* out = (float*)d_out;

    const int QSMEM = 4 * 128 * STR2 * 2;    // 73728 B (2 buf x (A+B))
    const int ESMEM = 2 * 128 * STRQ * 2;    // 102400 B
    cudaFuncSetAttribute(q_mma, cudaFuncAttributeMaxDynamicSharedMemorySize, QSMEM);
    cudaFuncSetAttribute(eh_mma, cudaFuncAttributeMaxDynamicSharedMemorySize, ESMEM);

    // order chosen so launch #6 (ncu -s 5 -c 1) is q_mma
    zero_kernel<<<1024, 256>>>();                           // 1
    wt_kernel<<<48, 256>>>(Wih, Whh, W1);                   // 2
    split_node<<<(NNP * 64 + 255) / 256, 256>>>(node);      // 3
    split_w2<<<64, 256>>>(W2);                              // 4
    split_edge<<<(NEP * 64 + 255) / 256, 256>>>(edge);      // 5
    q_mma<<<dim3(QC / 128, NNP / 128), 256, QSMEM>>>();     // 6  <- profiled
    eh_mma<<<NEP / 128, 256, ESMEM>>>(b1);                  // 7
    count_kernel<<<(NE + 255) / 256, 256>>>(src);           // 8
    scan_kernel<<<1, 1024>>>();                             // 9
    scatter_kernel<<<(NE + 255) / 256, 256>>>(src);         // 10
    msg_kernel<<<NN, 128>>>(node, b2, dst);                 // 11
    gru_ln_kernel<<<296, 256>>>(hidden, bih, bhh, gamma, beta, out); // 12
}

// round 9
// speedup vs baseline: 2.2559x; 1.0530x over previous
#include <cuda_runtime.h>
#include <cuda_bf16.h>
#include <cuda_fp16.h>
#include <math.h>
#include <cstdint>

#define H 64
#define NN 12000
#define NE 50000
#define EHD 128          // 2H
#define QC 8192          // H * 2H
#define NNP 12032        // NN padded to 128
#define NEP 50048        // NE padded to 128
#define KS 192           // split-K (hi|hi|lo)
#define STRQ 200         // smem row stride (bf16) for eh_mma
#define STR2 72          // smem row stride (bf16) for q_mma chunks

// ---------------- scratch (device globals; allocation-free) ----------------
__device__ __align__(16) float g_eh[NE * EHD];          // 25.6 MB
__device__ __align__(16) __half g_q[(size_t)NN * QC];   // 196 MB (fp16)
__device__ float g_agg[NN * H];
__device__ float g_WihT[64 * 192];
__device__ float g_WhhT[64 * 192];
__device__ __align__(16) __nv_bfloat16 g_Asplit[NNP * KS];   // node  hi|hi|lo
__device__ __align__(16) __nv_bfloat16 g_Bsplit[QC * KS];    // W2^T  hi|lo|hi
__device__ __align__(16) __nv_bfloat16 g_Esplit[NEP * KS];   // edge  hi|hi|lo
__device__ __align__(16) __nv_bfloat16 g_W1split[128 * KS];  // W1    hi|lo|hi
__device__ int g_cnt[NN];
__device__ int g_off[NN + 1];
__device__ int g_cur[NN];
__device__ int g_elist[NE];

__device__ __forceinline__ uint32_t smem_to_u32(const void* p) {
    uint32_t a;
    asm("{ .reg .u64 t; cvta.to.shared.u64 t, %1; cvt.u32.u64 %0, t; }" : "=r"(a) : "l"(p));
    return a;
}
__device__ __forceinline__ void cp16(void* s, const void* g) {
    uint32_t sa = smem_to_u32(s);
    asm volatile("cp.async.cg.shared.global [%0], [%1], 16;" :: "r"(sa), "l"(g));
}

// ---------------- 1: PREP (fused zero + transposes + bf16 splits) -----------
__global__ __launch_bounds__(256) void prep_kernel(const float* __restrict__ node,
                                                   const float* __restrict__ edge,
                                                   const float* __restrict__ W1,
                                                   const float* __restrict__ W2,
                                                   const float* __restrict__ Wih,
                                                   const float* __restrict__ Whh) {
    __shared__ float Ws[64 * 128];
    int b = blockIdx.x;
    int t = threadIdx.x;
    if (b < 64) {
        // ---- split_w2: B[n][k] = W2[k*8192 + n], row layout hi|lo|hi ----
        int n0 = b * 128;
        for (int j = t; j < 8192; j += 256) {
            int k = j >> 7, n = j & 127;
            Ws[k * 128 + n] = W2[(size_t)k * QC + n0 + n];
        }
        __syncthreads();
        for (int j = t; j < 8192; j += 256) {
            int n = j >> 6, k = j & 63;
            float x = Ws[k * 128 + n];
            __nv_bfloat16 hi = __float2bfloat16(x);
            __nv_bfloat16 lo = __float2bfloat16(x - __bfloat162float(hi));
            size_t base = (size_t)(n0 + n) * KS;
            g_Bsplit[base + k] = hi;
            g_Bsplit[base + 64 + k] = lo;
            g_Bsplit[base + 128 + k] = hi;
        }
        return;
    }
    int i0 = (b - 64) * 256 + t;
    int stride = (gridDim.x - 64) * 256;
    for (int j = i0; j < NN * H; j += stride) g_agg[j] = 0.f;
    for (int j = i0; j < NN; j += stride) g_cnt[j] = 0;
    for (int j = i0; j < 192 * 64; j += stride) {
        int r = j >> 6, h = j & 63;
        g_WihT[h * 192 + r] = Wih[j];
        g_WhhT[h * 192 + r] = Whh[j];
    }
    for (int j = i0; j < 128 * 64; j += stride) {
        int n = j >> 6, k = j & 63;
        float x = W1[j];
        __nv_bfloat16 hi = __float2bfloat16(x);
        __nv_bfloat16 lo = __float2bfloat16(x - __bfloat162float(hi));
        g_W1split[n * KS + k] = hi;
        g_W1split[n * KS + 64 + k] = lo;
        g_W1split[n * KS + 128 + k] = hi;
    }
    for (int j = i0; j < NNP * 64; j += stride) {
        int n = j >> 6, h = j & 63;
        float x = (n < NN) ? node[n * 64 + h] : 0.f;
        __nv_bfloat16 hi = __float2bfloat16(x);
        __nv_bfloat16 lo = __float2bfloat16(x - __bfloat162float(hi));
        g_Asplit[n * KS + h] = hi;
        g_Asplit[n * KS + 64 + h] = hi;
        g_Asplit[n * KS + 128 + h] = lo;
    }
    for (int j = i0; j < NEP * 64; j += stride) {
        int n = j >> 6, h = j & 63;
        float x = (n < NE) ? edge[n * 64 + h] : 0.f;
        __nv_bfloat16 hi = __float2bfloat16(x);
        __nv_bfloat16 lo = __float2bfloat16(x - __bfloat162float(hi));
        g_Esplit[n * KS + h] = hi;
        g_Esplit[n * KS + 64 + h] = hi;
        g_Esplit[n * KS + 128 + h] = lo;
    }
}

// ---------------- CSR by src ----------------
__global__ void count_kernel(const int* __restrict__ src) {
    int e = blockIdx.x * blockDim.x + threadIdx.x;
    if (e < NE) atomicAdd(&g_cnt[src[e]], 1);
}

__global__ void scan_kernel() {
    __shared__ int sm[1024];
    int tid = threadIdx.x;
    const int C = 12;
    int base = tid * C;
    int loc[C];
    int s = 0;
#pragma unroll
    for (int i = 0; i < C; i++) {
        int v = (base + i < NN) ? g_cnt[base + i] : 0;
        loc[i] = s;
        s += v;
    }
    sm[tid] = s;
    __syncthreads();
    for (int d = 1; d < 1024; d <<= 1) {
        int v = (tid >= d) ? sm[tid - d] : 0;
        __syncthreads();
        if (tid >= d) sm[tid] += v;
        __syncthreads();
    }
    int ex = sm[tid] - s;
#pragma unroll
    for (int i = 0; i < C; i++) {
        if (base + i < NN) {
            g_off[base + i] = ex + loc[i];
            g_cur[base + i] = ex + loc[i];
        }
    }
    if (tid == 1023) g_off[NN] = sm[1023];
}

__global__ void scatter_kernel(const int* __restrict__ src) {
    int e = blockIdx.x * blockDim.x + threadIdx.x;
    if (e < NE) {
        int p = atomicAdd(&g_cur[src[e]], 1);
        g_elist[p] = e;
    }
}

// ---------------- q GEMM on mma.sync, cp.async pipelined, fp16 out ----------
__global__ __launch_bounds__(256) void q_mma() {
    extern __shared__ __nv_bfloat16 smq[];
    __nv_bfloat16* As = smq;               // [2][128][STR2]
    __nv_bfloat16* Bs = smq + 2 * 128 * STR2;
    int n0 = blockIdx.x * 128, m0 = blockIdx.y * 128;
    int tid = threadIdx.x;

    int w = tid >> 5, lane = tid & 31;
    int wm = (w & 3) * 32, wn = (w >> 2) * 64;
    int g = lane >> 3;
    int arow = (lane & 7) + (g & 1) * 8, aka = (g >> 1) * 8;
    int brow = (lane & 7) + (g >> 1) * 8, bka = (g & 1) * 8;

    float acc[2][8][4];
#pragma unroll
    for (int im = 0; im < 2; im++)
#pragma unroll
        for (int jn = 0; jn < 8; jn++)
#pragma unroll
            for (int c = 0; c < 4; c++) acc[im][jn][c] = 0.f;

#define STAGE(c) do { \
        int _buf = (c) & 1; \
        __nv_bfloat16* _Ad = As + _buf * 128 * STR2; \
        __nv_bfloat16* _Bd = Bs + _buf * 128 * STR2; \
        const __nv_bfloat16* _Ag = g_Asplit + (size_t)m0 * KS + (c) * 64; \
        const __nv_bfloat16* _Bg = g_Bsplit + (size_t)n0 * KS + (c) * 64; \
        _Pragma("unroll") \
        for (int _i = 0; _i < 4; _i++) { \
            int _idx = tid + _i * 256; \
            int _r = _idx >> 3, _j = _idx & 7; \
            cp16(_Ad + _r * STR2 + _j * 8, _Ag + (size_t)_r * KS + _j * 8); \
            cp16(_Bd + _r * STR2 + _j * 8, _Bg + (size_t)_r * KS + _j * 8); \
        } \
        asm volatile("cp.async.commit_group;"); \
    } while (0)

    STAGE(0);
#pragma unroll
    for (int c = 0; c < 3; c++) {
        if (c + 1 < 3) STAGE(c + 1);
        if (c + 1 < 3) asm volatile("cp.async.wait_group 1;");
        else           asm volatile("cp.async.wait_group 0;");
        __syncthreads();
        const __nv_bfloat16* Ab = As + (c & 1) * 128 * STR2;
        const __nv_bfloat16* Bb = Bs + (c & 1) * 128 * STR2;
#pragma unroll
        for (int ks = 0; ks < 4; ks++) {
            int k0 = ks * 16;
            uint32_t a[2][4];
#pragma unroll
            for (int im = 0; im < 2; im++) {
                uint32_t addr = smem_to_u32(Ab + (wm + im * 16 + arow) * STR2 + k0 + aka);
                asm volatile("ldmatrix.sync.aligned.m8n8.x4.shared.b16 {%0,%1,%2,%3}, [%4];"
                             : "=r"(a[im][0]), "=r"(a[im][1]), "=r"(a[im][2]), "=r"(a[im][3])
                             : "r"(addr));
            }
            uint32_t b[4][4];
#pragma unroll
            for (int jb = 0; jb < 4; jb++) {
                uint32_t addr = smem_to_u32(Bb + (wn + jb * 16 + brow) * STR2 + k0 + bka);
                asm volatile("ldmatrix.sync.aligned.m8n8.x4.shared.b16 {%0,%1,%2,%3}, [%4];"
                             : "=r"(b[jb][0]), "=r"(b[jb][1]), "=r"(b[jb][2]), "=r"(b[jb][3])
                             : "r"(addr));
            }
#pragma unroll
            for (int im = 0; im < 2; im++)
#pragma unroll
                for (int jn = 0; jn < 8; jn++) {
                    uint32_t b0 = b[jn >> 1][(jn & 1) * 2];
                    uint32_t b1 = b[jn >> 1][(jn & 1) * 2 + 1];
                    asm volatile(
                        "mma.sync.aligned.m16n8k16.row.col.f32.bf16.bf16.f32 "
                        "{%0,%1,%2,%3}, {%4,%5,%6,%7}, {%8,%9}, {%0,%1,%2,%3};"
                        : "+f"(acc[im][jn][0]), "+f"(acc[im][jn][1]),
                          "+f"(acc[im][jn][2]), "+f"(acc[im][jn][3])
                        : "r"(a[im][0]), "r"(a[im][1]), "r"(a[im][2]), "r"(a[im][3]),
                          "r"(b0), "r"(b1));
                }
        }
        __syncthreads();
    }
#undef STAGE

    // fp16 epilogue
#pragma unroll
    for (int im = 0; im < 2; im++) {
        int m = m0 + wm + im * 16 + (lane >> 2);
#pragma unroll
        for (int jn = 0; jn < 8; jn++) {
            int c = n0 + wn + jn * 8 + (lane & 3) * 2;
            if (m < NN)
                *reinterpret_cast<__half2*>(&g_q[(size_t)m * QC + c]) =
                    __floats2half2_rn(acc[im][jn][0], acc[im][jn][1]);
            if (m + 8 < NN)
                *reinterpret_cast<__half2*>(&g_q[(size_t)(m + 8) * QC + c]) =
                    __floats2half2_rn(acc[im][jn][2], acc[im][jn][3]);
        }
    }
}

// ---------------- eh = relu(edge @ W1.T + b1) on mma.sync ----------------
__global__ __launch_bounds__(256, 2) void eh_mma(const float* __restrict__ b1) {
    extern __shared__ __nv_bfloat16 sme[];
    __nv_bfloat16* As = sme;               // [128][STRQ]
    __nv_bfloat16* Bs = sme + 128 * STRQ;  // [128][STRQ]
    int m0 = blockIdx.x * 128;
    int tid = threadIdx.x;

    for (int i = tid; i < 3072; i += 256) {
        int r = i / 24, c = i % 24;
        *reinterpret_cast<uint4*>(As + r * STRQ + c * 8) =
            reinterpret_cast<const uint4*>(g_Esplit + (size_t)(m0 + r) * KS)[c];
        *reinterpret_cast<uint4*>(Bs + r * STRQ + c * 8) =
            reinterpret_cast<const uint4*>(g_W1split + (size_t)r * KS)[c];
    }
    __syncthreads();

    int w = tid >> 5, lane = tid & 31;
    int wm = (w & 3) * 32, wn = (w >> 2) * 64;
    int g = lane >> 3;
    int arow = (lane & 7) + (g & 1) * 8, aka = (g >> 1) * 8;
    int brow = (lane & 7) + (g >> 1) * 8, bka = (g & 1) * 8;

    float acc[2][8][4];
#pragma unroll
    for (int im = 0; im < 2; im++)
#pragma unroll
        for (int jn = 0; jn < 8; jn++)
#pragma unroll
            for (int c = 0; c < 4; c++) acc[im][jn][c] = 0.f;

#pragma unroll
    for (int kk = 0; kk < 12; kk++) {
        int k0 = kk * 16;
        uint32_t a[2][4];
#pragma unroll
        for (int im = 0; im < 2; im++) {
            uint32_t addr = smem_to_u32(As + (wm + im * 16 + arow) * STRQ + k0 + aka);
            asm volatile("ldmatrix.sync.aligned.m8n8.x4.shared.b16 {%0,%1,%2,%3}, [%4];"
                         : "=r"(a[im][0]), "=r"(a[im][1]), "=r"(a[im][2]), "=r"(a[im][3])
                         : "r"(addr));
        }
        uint32_t b[4][4];
#pragma unroll
        for (int jb = 0; jb < 4; jb++) {
            uint32_t addr = smem_to_u32(Bs + (wn + jb * 16 + brow) * STRQ + k0 + bka);
            asm volatile("ldmatrix.sync.aligned.m8n8.x4.shared.b16 {%0,%1,%2,%3}, [%4];"
                         : "=r"(b[jb][0]), "=r"(b[jb][1]), "=r"(b[jb][2]), "=r"(b[jb][3])
                         : "r"(addr));
        }
#pragma unroll
        for (int im = 0; im < 2; im++)
#pragma unroll
            for (int jn = 0; jn < 8; jn++) {
                uint32_t b0 = b[jn >> 1][(jn & 1) * 2];
                uint32_t b1 = b[jn >> 1][(jn & 1) * 2 + 1];
                asm volatile(
                    "mma.sync.aligned.m16n8k16.row.col.f32.bf16.bf16.f32 "
                    "{%0,%1,%2,%3}, {%4,%5,%6,%7}, {%8,%9}, {%0,%1,%2,%3};"
                    : "+f"(acc[im][jn][0]), "+f"(acc[im][jn][1]),
                      "+f"(acc[im][jn][2]), "+f"(acc[im][jn][3])
                    : "r"(a[im][0]), "r"(a[im][1]), "r"(a[im][2]), "r"(a[im][3]),
                      "r"(b0), "r"(b1));
            }
    }

#pragma unroll
    for (int im = 0; im < 2; im++) {
        int m = m0 + wm + im * 16 + (lane >> 2);
#pragma unroll
        for (int jn = 0; jn < 8; jn++) {
            int c = wn + jn * 8 + (lane & 3) * 2;
            float bb0 = b1[c], bb1 = b1[c + 1];
            if (m < NE)
                *reinterpret_cast<float2*>(&g_eh[(size_t)m * EHD + c]) =
                    make_float2(fmaxf(acc[im][jn][0] + bb0, 0.f),
                                fmaxf(acc[im][jn][1] + bb1, 0.f));
            if (m + 8 < NE)
                *reinterpret_cast<float2*>(&g_eh[(size_t)(m + 8) * EHD + c]) =
                    make_float2(fmaxf(acc[im][jn][2] + bb0, 0.f),
                                fmaxf(acc[im][jn][3] + bb1, 0.f));
        }
    }
}

// ---------------- msg: per-src-node message + scatter-add (q in fp16) -------
__global__ __launch_bounds__(128) void msg_kernel(const float* __restrict__ node,
                                                  const float* __restrict__ b2,
                                                  const int* __restrict__ dst) {
    __shared__ float q_s[64 * 132];
    __shared__ float x_s[64];
    __shared__ float bb_s[64];
    int n = blockIdx.x;
    int t = threadIdx.x;

    int beg = g_off[n], end = g_off[n + 1];
    if (beg == end) return;

    // 8192 halves per node = 1024 uint4; one k-row (128 halves) = 16 uint4
    const uint4* qn = reinterpret_cast<const uint4*>(g_q + (size_t)n * QC);
#pragma unroll 4
    for (int j = t; j < 1024; j += 128) {
        int k = j >> 4, c16 = j & 15;        // FIXED: 16 uint4 per k-row
        uint4 v = qn[j];
        const __half2* h2 = reinterpret_cast<const __half2*>(&v);
        float* dstp = &q_s[k * 132 + c16 * 8];
#pragma unroll
        for (int p = 0; p < 4; p++) {
            float2 f = __half22float2(h2[p]);
            dstp[p * 2] = f.x;
            dstp[p * 2 + 1] = f.y;
        }
    }
    if (t < 64) x_s[t] = node[n * 64 + t];
    __syncthreads();
    if (t < 64) {
        float bb = 0.f;
#pragma unroll 8
        for (int h = 0; h < 64; h++) bb = fmaf(x_s[h], b2[h * 64 + t], bb);
        bb_s[t] = bb;
    }
    __syncthreads();

    int k = t >> 1, half = t & 1;
    const float4* qk = reinterpret_cast<const float4*>(&q_s[k * 132 + half * 64]);
    for (int ei = beg; ei < end; ei++) {
        int e = g_elist[ei];
        const float4* ep = reinterpret_cast<const float4*>(g_eh + (size_t)e * EHD) + half * 16;
        float acc = 0.f;
#pragma unroll
        for (int g = 0; g < 16; g++) {
            float4 ev = ep[g];
            float4 qv = qk[g];
            acc += ev.x * qv.x + ev.y * qv.y + ev.z * qv.z + ev.w * qv.w;
        }
        acc += __shfl_xor_sync(0xffffffffu, acc, 1);
        if (half == 0) {
            int d = dst[e];
            atomicAdd(&g_agg[d * 64 + k], acc + bb_s[k]);
        }
    }
}

// ---------------- relu(agg) -> GRU -> LayerNorm ----------------
__global__ __launch_bounds__(256) void gru_ln_kernel(const float* __restrict__ hidden,
                                                     const float* __restrict__ bih,
                                                     const float* __restrict__ bhh,
                                                     const float* __restrict__ gamma,
                                                     const float* __restrict__ beta,
                                                     float* __restrict__ out) {
    __shared__ float xs[4][64], hs[4][64];
    __shared__ float redA[8], redB[8];
    int t = threadIdx.x;
    int sub = t >> 6, k = t & 63;
    int wid = t >> 5, lane = t & 31;
    float bi0 = bih[k], bi1 = bih[64 + k], bi2 = bih[128 + k];
    float bh0 = bhh[k], bh1 = bhh[64 + k], bh2 = bhh[128 + k];
    float gm = gamma[k], bt = beta[k];

    for (int n0 = blockIdx.x * 4; n0 < NN; n0 += gridDim.x * 4) {
        int n = n0 + sub;
        float x = fmaxf(g_agg[n * 64 + k], 0.f);
        float hv = hidden[n * 64 + k];
        xs[sub][k] = x;
        hs[sub][k] = hv;
        __syncthreads();
        float gi0 = bi0, gi1 = bi1, gi2 = bi2;
        float gh0 = bh0, gh1 = bh1, gh2 = bh2;
#pragma unroll 8
        for (int h = 0; h < 64; h++) {
            float xv = xs[sub][h], hh = hs[sub][h];
            const float* wi = &g_WihT[h * 192];
            const float* wh = &g_WhhT[h * 192];
            gi0 = fmaf(xv, wi[k], gi0);
            gi1 = fmaf(xv, wi[64 + k], gi1);
            gi2 = fmaf(xv, wi[128 + k], gi2);
            gh0 = fmaf(hh, wh[k], gh0);
            gh1 = fmaf(hh, wh[64 + k], gh1);
            gh2 = fmaf(hh, wh[128 + k], gh2);
        }
        float r = 1.f / (1.f + expf(-(gi0 + gh0)));
        float z = 1.f / (1.f + expf(-(gi1 + gh1)));
        float nn2 = tanhf(gi2 + r * gh2);
        float o = (1.f - z) * nn2 + z * hv;

        float s1 = o, s2 = o * o;
#pragma unroll
        for (int d = 16; d > 0; d >>= 1) {
            s1 += __shfl_xor_sync(0xffffffffu, s1, d);
            s2 += __shfl_xor_sync(0xffffffffu, s2, d);
        }
        if (lane == 0) { redA[wid] = s1; redB[wid] = s2; }
        __syncthreads();
        float S1 = redA[sub * 2] + redA[sub * 2 + 1];
        float S2 = redB[sub * 2] + redB[sub * 2 + 1];
        float mu = S1 * 0.015625f;
        float var = S2 * 0.015625f - mu * mu;
        out[n * 64 + k] = (o - mu) * rsqrtf(var + 1e-5f) * gm + bt;
        __syncthreads();
    }
}

// ---------------- launch ----------------
extern "C" void kernel_launch(void* const* d_in, const int* in_sizes, int n_in,
                              void* d_out, int out_size) {
    const float* node   = (const float*)d_in[0];
    const float* edge   = (const float*)d_in[1];
    const float* hidden = (const float*)d_in[2];
    const int*   src    = (const int*)d_in[3];
    const int*   dst    = (const int*)d_in[4];
    const float* W1     = (const float*)d_in[5];
    const float* b1     = (const float*)d_in[6];
    const float* W2     = (const float*)d_in[7];
    const float* b2     = (const float*)d_in[8];
    const float* Wih    = (const float*)d_in[9];
    const float* Whh    = (const float*)d_in[10];
    const float* bih    = (const float*)d_in[11];
    const float* bhh    = (const float*)d_in[12];
    const float* gamma  = (const float*)d_in[13];
    const float* beta   = (const float*)d_in[14];
    float* out = (float*)d_out;

    const int QSMEM = 4 * 128 * STR2 * 2;    // 73728 B
    const int ESMEM = 2 * 128 * STRQ * 2;    // 102400 B
    cudaFuncSetAttribute(q_mma, cudaFuncAttributeMaxDynamicSharedMemorySize, QSMEM);
    cudaFuncSetAttribute(eh_mma, cudaFuncAttributeMaxDynamicSharedMemorySize, ESMEM);

    // launch #4 is the one ncu captures -> q_mma
    prep_kernel<<<64 + 512, 256>>>(node, edge, W1, W2, Wih, Whh);   // 1
    count_kernel<<<(NE + 255) / 256, 256>>>(src);                   // 2
    scan_kernel<<<1, 1024>>>();                                     // 3
    q_mma<<<dim3(QC / 128, NNP / 128), 256, QSMEM>>>();             // 4 <- profiled
    eh_mma<<<NEP / 128, 256, ESMEM>>>(b1);                          // 5
    scatter_kernel<<<(NE + 255) / 256, 256>>>(src);                 // 6
    msg_kernel<<<NN, 128>>>(node, b2, dst);                         // 7
    gru_ln_kernel<<<296, 256>>>(hidden, bih, bhh, gamma, beta, out);// 8
}

// round 10
// speedup vs baseline: 2.2561x; 1.0001x over previous
#include <cuda_runtime.h>
#include <cuda_bf16.h>
#include <cuda_fp16.h>
#include <math.h>
#include <cstdint>

#define H 64
#define NN 12000
#define NE 50000
#define EHD 128          // 2H
#define QC 8192          // H * 2H
#define NNP 12032        // NN padded to 128
#define NEP 50048        // NE padded to 128
#define KS 192           // split-K (hi|hi|lo)
#define STRQ 200         // smem row stride (bf16) for eh_mma
#define STR2 72          // smem row stride (bf16) for q_mma chunks

// ---------------- scratch (device globals; allocation-free) ----------------
__device__ __align__(16) float g_eh[NE * EHD];          // 25.6 MB
__device__ __align__(16) __half g_q[(size_t)NN * QC];   // 196 MB (fp16)
__device__ float g_agg[NN * H];
__device__ float g_WihT[64 * 192];
__device__ float g_WhhT[64 * 192];
__device__ __align__(16) __nv_bfloat16 g_Asplit[NNP * KS];   // node  hi|hi|lo
__device__ __align__(16) __nv_bfloat16 g_Bsplit[QC * KS];    // W2^T  hi|lo|hi
__device__ __align__(16) __nv_bfloat16 g_Esplit[NEP * KS];   // edge  hi|hi|lo
__device__ __align__(16) __nv_bfloat16 g_W1split[128 * KS];  // W1    hi|lo|hi
__device__ int g_cnt[NN];
__device__ int g_off[NN + 1];
__device__ int g_cur[NN];
__device__ int g_elist[NE];

__device__ __forceinline__ uint32_t smem_to_u32(const void* p) {
    uint32_t a;
    asm("{ .reg .u64 t; cvta.to.shared.u64 t, %1; cvt.u32.u64 %0, t; }" : "=r"(a) : "l"(p));
    return a;
}
__device__ __forceinline__ void cp16(void* s, const void* g) {
    uint32_t sa = smem_to_u32(s);
    asm volatile("cp.async.cg.shared.global [%0], [%1], 16;" :: "r"(sa), "l"(g));
}

// ---------------- 1: PREP (fused zero + transposes + bf16 splits) -----------
__global__ __launch_bounds__(256) void prep_kernel(const float* __restrict__ node,
                                                   const float* __restrict__ edge,
                                                   const float* __restrict__ W1,
                                                   const float* __restrict__ W2,
                                                   const float* __restrict__ Wih,
                                                   const float* __restrict__ Whh) {
    __shared__ float Ws[64 * 128];
    int b = blockIdx.x;
    int t = threadIdx.x;
    if (b < 64) {
        int n0 = b * 128;
        for (int j = t; j < 8192; j += 256) {
            int k = j >> 7, n = j & 127;
            Ws[k * 128 + n] = W2[(size_t)k * QC + n0 + n];
        }
        __syncthreads();
        for (int j = t; j < 8192; j += 256) {
            int n = j >> 6, k = j & 63;
            float x = Ws[k * 128 + n];
            __nv_bfloat16 hi = __float2bfloat16(x);
            __nv_bfloat16 lo = __float2bfloat16(x - __bfloat162float(hi));
            size_t base = (size_t)(n0 + n) * KS;
            g_Bsplit[base + k] = hi;
            g_Bsplit[base + 64 + k] = lo;
            g_Bsplit[base + 128 + k] = hi;
        }
        return;
    }
    int i0 = (b - 64) * 256 + t;
    int stride = (gridDim.x - 64) * 256;
    for (int j = i0; j < NN * H; j += stride) g_agg[j] = 0.f;
    for (int j = i0; j < NN; j += stride) g_cnt[j] = 0;
    for (int j = i0; j < 192 * 64; j += stride) {
        int r = j >> 6, h = j & 63;
        g_WihT[h * 192 + r] = Wih[j];
        g_WhhT[h * 192 + r] = Whh[j];
    }
    for (int j = i0; j < 128 * 64; j += stride) {
        int n = j >> 6, k = j & 63;
        float x = W1[j];
        __nv_bfloat16 hi = __float2bfloat16(x);
        __nv_bfloat16 lo = __float2bfloat16(x - __bfloat162float(hi));
        g_W1split[n * KS + k] = hi;
        g_W1split[n * KS + 64 + k] = lo;
        g_W1split[n * KS + 128 + k] = hi;
    }
    for (int j = i0; j < NNP * 64; j += stride) {
        int n = j >> 6, h = j & 63;
        float x = (n < NN) ? node[n * 64 + h] : 0.f;
        __nv_bfloat16 hi = __float2bfloat16(x);
        __nv_bfloat16 lo = __float2bfloat16(x - __bfloat162float(hi));
        g_Asplit[n * KS + h] = hi;
        g_Asplit[n * KS + 64 + h] = hi;
        g_Asplit[n * KS + 128 + h] = lo;
    }
    for (int j = i0; j < NEP * 64; j += stride) {
        int n = j >> 6, h = j & 63;
        float x = (n < NE) ? edge[n * 64 + h] : 0.f;
        __nv_bfloat16 hi = __float2bfloat16(x);
        __nv_bfloat16 lo = __float2bfloat16(x - __bfloat162float(hi));
        g_Esplit[n * KS + h] = hi;
        g_Esplit[n * KS + 64 + h] = hi;
        g_Esplit[n * KS + 128 + h] = lo;
    }
}

// ---------------- CSR by src ----------------
__global__ void count_kernel(const int* __restrict__ src) {
    int e = blockIdx.x * blockDim.x + threadIdx.x;
    if (e < NE) atomicAdd(&g_cnt[src[e]], 1);
}

__global__ void scan_kernel() {
    __shared__ int sm[1024];
    int tid = threadIdx.x;
    const int C = 12;
    int base = tid * C;
    int loc[C];
    int s = 0;
#pragma unroll
    for (int i = 0; i < C; i++) {
        int v = (base + i < NN) ? g_cnt[base + i] : 0;
        loc[i] = s;
        s += v;
    }
    sm[tid] = s;
    __syncthreads();
    for (int d = 1; d < 1024; d <<= 1) {
        int v = (tid >= d) ? sm[tid - d] : 0;
        __syncthreads();
        if (tid >= d) sm[tid] += v;
        __syncthreads();
    }
    int ex = sm[tid] - s;
#pragma unroll
    for (int i = 0; i < C; i++) {
        if (base + i < NN) {
            g_off[base + i] = ex + loc[i];
            g_cur[base + i] = ex + loc[i];
        }
    }
    if (tid == 1023) g_off[NN] = sm[1023];
}

__global__ void scatter_kernel(const int* __restrict__ src) {
    int e = blockIdx.x * blockDim.x + threadIdx.x;
    if (e < NE) {
        int p = atomicAdd(&g_cur[src[e]], 1);
        g_elist[p] = e;
    }
}

// ---------------- q GEMM on mma.sync, cp.async pipelined, fp16 out ----------
// __launch_bounds__(256, 2): cap regs at 128 so 2 CTAs fit per SM
__global__ __launch_bounds__(256, 2) void q_mma() {
    extern __shared__ __nv_bfloat16 smq[];
    __nv_bfloat16* As = smq;               // [2][128][STR2]
    __nv_bfloat16* Bs = smq + 2 * 128 * STR2;
    int n0 = blockIdx.x * 128, m0 = blockIdx.y * 128;
    int tid = threadIdx.x;

    int w = tid >> 5, lane = tid & 31;
    int wm = (w & 3) * 32, wn = (w >> 2) * 64;
    int g = lane >> 3;
    int arow = (lane & 7) + (g & 1) * 8, aka = (g >> 1) * 8;
    int brow = (lane & 7) + (g >> 1) * 8, bka = (g & 1) * 8;

    float acc[2][8][4];
#pragma unroll
    for (int im = 0; im < 2; im++)
#pragma unroll
        for (int jn = 0; jn < 8; jn++)
#pragma unroll
            for (int c = 0; c < 4; c++) acc[im][jn][c] = 0.f;

#define STAGE(c) do { \
        int _buf = (c) & 1; \
        __nv_bfloat16* _Ad = As + _buf * 128 * STR2; \
        __nv_bfloat16* _Bd = Bs + _buf * 128 * STR2; \
        const __nv_bfloat16* _Ag = g_Asplit + (size_t)m0 * KS + (c) * 64; \
        const __nv_bfloat16* _Bg = g_Bsplit + (size_t)n0 * KS + (c) * 64; \
        _Pragma("unroll") \
        for (int _i = 0; _i < 4; _i++) { \
            int _idx = tid + _i * 256; \
            int _r = _idx >> 3, _j = _idx & 7; \
            cp16(_Ad + _r * STR2 + _j * 8, _Ag + (size_t)_r * KS + _j * 8); \
            cp16(_Bd + _r * STR2 + _j * 8, _Bg + (size_t)_r * KS + _j * 8); \
        } \
        asm volatile("cp.async.commit_group;"); \
    } while (0)

    STAGE(0);
#pragma unroll
    for (int c = 0; c < 3; c++) {
        if (c + 1 < 3) STAGE(c + 1);
        if (c + 1 < 3) asm volatile("cp.async.wait_group 1;");
        else           asm volatile("cp.async.wait_group 0;");
        __syncthreads();
        const __nv_bfloat16* Ab = As + (c & 1) * 128 * STR2;
        const __nv_bfloat16* Bb = Bs + (c & 1) * 128 * STR2;
#pragma unroll
        for (int ks = 0; ks < 4; ks++) {
            int k0 = ks * 16;
            uint32_t a[2][4];
#pragma unroll
            for (int im = 0; im < 2; im++) {
                uint32_t addr = smem_to_u32(Ab + (wm + im * 16 + arow) * STR2 + k0 + aka);
                asm volatile("ldmatrix.sync.aligned.m8n8.x4.shared.b16 {%0,%1,%2,%3}, [%4];"
                             : "=r"(a[im][0]), "=r"(a[im][1]), "=r"(a[im][2]), "=r"(a[im][3])
                             : "r"(addr));
            }
            // load one B fragment at a time (4 regs live instead of 16)
#pragma unroll
            for (int jb = 0; jb < 4; jb++) {
                uint32_t b0, b1, b2, b3;
                uint32_t addr = smem_to_u32(Bb + (wn + jb * 16 + brow) * STR2 + k0 + bka);
                asm volatile("ldmatrix.sync.aligned.m8n8.x4.shared.b16 {%0,%1,%2,%3}, [%4];"
                             : "=r"(b0), "=r"(b1), "=r"(b2), "=r"(b3) : "r"(addr));
#pragma unroll
                for (int im = 0; im < 2; im++) {
                    asm volatile(
                        "mma.sync.aligned.m16n8k16.row.col.f32.bf16.bf16.f32 "
                        "{%0,%1,%2,%3}, {%4,%5,%6,%7}, {%8,%9}, {%0,%1,%2,%3};"
                        : "+f"(acc[im][jb * 2][0]), "+f"(acc[im][jb * 2][1]),
                          "+f"(acc[im][jb * 2][2]), "+f"(acc[im][jb * 2][3])
                        : "r"(a[im][0]), "r"(a[im][1]), "r"(a[im][2]), "r"(a[im][3]),
                          "r"(b0), "r"(b1));
                    asm volatile(
                        "mma.sync.aligned.m16n8k16.row.col.f32.bf16.bf16.f32 "
                        "{%0,%1,%2,%3}, {%4,%5,%6,%7}, {%8,%9}, {%0,%1,%2,%3};"
                        : "+f"(acc[im][jb * 2 + 1][0]), "+f"(acc[im][jb * 2 + 1][1]),
                          "+f"(acc[im][jb * 2 + 1][2]), "+f"(acc[im][jb * 2 + 1][3])
                        : "r"(a[im][0]), "r"(a[im][1]), "r"(a[im][2]), "r"(a[im][3]),
                          "r"(b2), "r"(b3));
                }
            }
        }
        __syncthreads();
    }
#undef STAGE

    // fp16 epilogue
#pragma unroll
    for (int im = 0; im < 2; im++) {
        int m = m0 + wm + im * 16 + (lane >> 2);
#pragma unroll
        for (int jn = 0; jn < 8; jn++) {
            int c = n0 + wn + jn * 8 + (lane & 3) * 2;
            if (m < NN)
                *reinterpret_cast<__half2*>(&g_q[(size_t)m * QC + c]) =
                    __floats2half2_rn(acc[im][jn][0], acc[im][jn][1]);
            if (m + 8 < NN)
                *reinterpret_cast<__half2*>(&g_q[(size_t)(m + 8) * QC + c]) =
                    __floats2half2_rn(acc[im][jn][2], acc[im][jn][3]);
        }
    }
}

// ---------------- eh = relu(edge @ W1.T + b1) on mma.sync ----------------
__global__ __launch_bounds__(256, 2) void eh_mma(const float* __restrict__ b1) {
    extern __shared__ __nv_bfloat16 sme[];
    __nv_bfloat16* As = sme;               // [128][STRQ]
    __nv_bfloat16* Bs = sme + 128 * STRQ;  // [128][STRQ]
    int m0 = blockIdx.x * 128;
    int tid = threadIdx.x;

    for (int i = tid; i < 3072; i += 256) {
        int r = i / 24, c = i % 24;
        *reinterpret_cast<uint4*>(As + r * STRQ + c * 8) =
            reinterpret_cast<const uint4*>(g_Esplit + (size_t)(m0 + r) * KS)[c];
        *reinterpret_cast<uint4*>(Bs + r * STRQ + c * 8) =
            reinterpret_cast<const uint4*>(g_W1split + (size_t)r * KS)[c];
    }
    __syncthreads();

    int w = tid >> 5, lane = tid & 31;
    int wm = (w & 3) * 32, wn = (w >> 2) * 64;
    int g = lane >> 3;
    int arow = (lane & 7) + (g & 1) * 8, aka = (g >> 1) * 8;
    int brow = (lane & 7) + (g >> 1) * 8, bka = (g & 1) * 8;

    float acc[2][8][4];
#pragma unroll
    for (int im = 0; im < 2; im++)
#pragma unroll
        for (int jn = 0; jn < 8; jn++)
#pragma unroll
            for (int c = 0; c < 4; c++) acc[im][jn][c] = 0.f;

#pragma unroll
    for (int kk = 0; kk < 12; kk++) {
        int k0 = kk * 16;
        uint32_t a[2][4];
#pragma unroll
        for (int im = 0; im < 2; im++) {
            uint32_t addr = smem_to_u32(As + (wm + im * 16 + arow) * STRQ + k0 + aka);
            asm volatile("ldmatrix.sync.aligned.m8n8.x4.shared.b16 {%0,%1,%2,%3}, [%4];"
                         : "=r"(a[im][0]), "=r"(a[im][1]), "=r"(a[im][2]), "=r"(a[im][3])
                         : "r"(addr));
        }
#pragma unroll
        for (int jb = 0; jb < 4; jb++) {
            uint32_t b0, b1r, b2, b3;
            uint32_t addr = smem_to_u32(Bs + (wn + jb * 16 + brow) * STRQ + k0 + bka);
            asm volatile("ldmatrix.sync.aligned.m8n8.x4.shared.b16 {%0,%1,%2,%3}, [%4];"
                         : "=r"(b0), "=r"(b1r), "=r"(b2), "=r"(b3) : "r"(addr));
#pragma unroll
            for (int im = 0; im < 2; im++) {
                asm volatile(
                    "mma.sync.aligned.m16n8k16.row.col.f32.bf16.bf16.f32 "
                    "{%0,%1,%2,%3}, {%4,%5,%6,%7}, {%8,%9}, {%0,%1,%2,%3};"
                    : "+f"(acc[im][jb * 2][0]), "+f"(acc[im][jb * 2][1]),
                      "+f"(acc[im][jb * 2][2]), "+f"(acc[im][jb * 2][3])
                    : "r"(a[im][0]), "r"(a[im][1]), "r"(a[im][2]), "r"(a[im][3]),
                      "r"(b0), "r"(b1r));
                asm volatile(
                    "mma.sync.aligned.m16n8k16.row.col.f32.bf16.bf16.f32 "
                    "{%0,%1,%2,%3}, {%4,%5,%6,%7}, {%8,%9}, {%0,%1,%2,%3};"
                    : "+f"(acc[im][jb * 2 + 1][0]), "+f"(acc[im][jb * 2 + 1][1]),
                      "+f"(acc[im][jb * 2 + 1][2]), "+f"(acc[im][jb * 2 + 1][3])
                    : "r"(a[im][0]), "r"(a[im][1]), "r"(a[im][2]), "r"(a[im][3]),
                      "r"(b2), "r"(b3));
            }
        }
    }

#pragma unroll
    for (int im = 0; im < 2; im++) {
        int m = m0 + wm + im * 16 + (lane >> 2);
#pragma unroll
        for (int jn = 0; jn < 8; jn++) {
            int c = wn + jn * 8 + (lane & 3) * 2;
            float bb0 = b1[c], bb1 = b1[c + 1];
            if (m < NE)
                *reinterpret_cast<float2*>(&g_eh[(size_t)m * EHD + c]) =
                    make_float2(fmaxf(acc[im][jn][0] + bb0, 0.f),
                                fmaxf(acc[im][jn][1] + bb1, 0.f));
            if (m + 8 < NE)
                *reinterpret_cast<float2*>(&g_eh[(size_t)(m + 8) * EHD + c]) =
                    make_float2(fmaxf(acc[im][jn][2] + bb0, 0.f),
                                fmaxf(acc[im][jn][3] + bb1, 0.f));
        }
    }
}

// ---------------- msg: per-src-node message + scatter-add (q in fp16) -------
__global__ __launch_bounds__(128) void msg_kernel(const float* __restrict__ node,
                                                  const float* __restrict__ b2,
                                                  const int* __restrict__ dst) {
    __shared__ float q_s[64 * 132];
    __shared__ float x_s[64];
    __shared__ float bb_s[64];
    int n = blockIdx.x;
    int t = threadIdx.x;

    int beg = g_off[n], end = g_off[n + 1];
    if (beg == end) return;

    const uint4* qn = reinterpret_cast<const uint4*>(g_q + (size_t)n * QC);
#pragma unroll 4
    for (int j = t; j < 1024; j += 128) {
        int k = j >> 4, c16 = j & 15;
        uint4 v = qn[j];
        const __half2* h2 = reinterpret_cast<const __half2*>(&v);
        float* dstp = &q_s[k * 132 + c16 * 8];
#pragma unroll
        for (int p = 0; p < 4; p++) {
            float2 f = __half22float2(h2[p]);
            dstp[p * 2] = f.x;
            dstp[p * 2 + 1] = f.y;
        }
    }
    if (t < 64) x_s[t] = node[n * 64 + t];
    __syncthreads();
    if (t < 64) {
        float bb = 0.f;
#pragma unroll 8
        for (int h = 0; h < 64; h++) bb = fmaf(x_s[h], b2[h * 64 + t], bb);
        bb_s[t] = bb;
    }
    __syncthreads();

    int k = t >> 1, half = t & 1;
    const float4* qk = reinterpret_cast<const float4*>(&q_s[k * 132 + half * 64]);
    for (int ei = beg; ei < end; ei++) {
        int e = g_elist[ei];
        const float4* ep = reinterpret_cast<const float4*>(g_eh + (size_t)e * EHD) + half * 16;
        float acc = 0.f;
#pragma unroll
        for (int g = 0; g < 16; g++) {
            float4 ev = ep[g];
            float4 qv = qk[g];
            acc += ev.x * qv.x + ev.y * qv.y + ev.z * qv.z + ev.w * qv.w;
        }
        acc += __shfl_xor_sync(0xffffffffu, acc, 1);
        if (half == 0) {
            int d = dst[e];
            atomicAdd(&g_agg[d * 64 + k], acc + bb_s[k]);
        }
    }
}

// ---------------- relu(agg) -> GRU -> LayerNorm ----------------
__global__ __launch_bounds__(256) void gru_ln_kernel(const float* __restrict__ hidden,
                                                     const float* __restrict__ bih,
                                                     const float* __restrict__ bhh,
                                                     const float* __restrict__ gamma,
                                                     const float* __restrict__ beta,
                                                     float* __restrict__ out) {
    __shared__ float xs[4][64], hs[4][64];
    __shared__ float redA[8], redB[8];
    int t = threadIdx.x;
    int sub = t >> 6, k = t & 63;
    int wid = t >> 5, lane = t & 31;
    float bi0 = bih[k], bi1 = bih[64 + k], bi2 = bih[128 + k];
    float bh0 = bhh[k], bh1 = bhh[64 + k], bh2 = bhh[128 + k];
    float gm = gamma[k], bt = beta[k];

    for (int n0 = blockIdx.x * 4; n0 < NN; n0 += gridDim.x * 4) {
        int n = n0 + sub;
        float x = fmaxf(g_agg[n * 64 + k], 0.f);
        float hv = hidden[n * 64 + k];
        xs[sub][k] = x;
        hs[sub][k] = hv;
        __syncthreads();
        float gi0 = bi0, gi1 = bi1, gi2 = bi2;
        float gh0 = bh0, gh1 = bh1, gh2 = bh2;
#pragma unroll 8
        for (int h = 0; h < 64; h++) {
            float xv = xs[sub][h], hh = hs[sub][h];
            const float* wi = &g_WihT[h * 192];
            const float* wh = &g_WhhT[h * 192];
            gi0 = fmaf(xv, wi[k], gi0);
            gi1 = fmaf(xv, wi[64 + k], gi1);
            gi2 = fmaf(xv, wi[128 + k], gi2);
            gh0 = fmaf(hh, wh[k], gh0);
            gh1 = fmaf(hh, wh[64 + k], gh1);
            gh2 = fmaf(hh, wh[128 + k], gh2);
        }
        float r = 1.f / (1.f + expf(-(gi0 + gh0)));
        float z = 1.f / (1.f + expf(-(gi1 + gh1)));
        float nn2 = tanhf(gi2 + r * gh2);
        float o = (1.f - z) * nn2 + z * hv;

        float s1 = o, s2 = o * o;
#pragma unroll
        for (int d = 16; d > 0; d >>= 1) {
            s1 += __shfl_xor_sync(0xffffffffu, s1, d);
            s2 += __shfl_xor_sync(0xffffffffu, s2, d);
        }
        if (lane == 0) { redA[wid] = s1; redB[wid] = s2; }
        __syncthreads();
        float S1 = redA[sub * 2] + redA[sub * 2 + 1];
        float S2 = redB[sub * 2] + redB[sub * 2 + 1];
        float mu = S1 * 0.015625f;
        float var = S2 * 0.015625f - mu * mu;
        out[n * 64 + k] = (o - mu) * rsqrtf(var + 1e-5f) * gm + bt;
        __syncthreads();
    }
}

// ---------------- launch ----------------
extern "C" void kernel_launch(void* const* d_in, const int* in_sizes, int n_in,
                              void* d_out, int out_size) {
    const float* node   = (const float*)d_in[0];
    const float* edge   = (const float*)d_in[1];
    const float* hidden = (const float*)d_in[2];
    const int*   src    = (const int*)d_in[3];
    const int*   dst    = (const int*)d_in[4];
    const float* W1     = (const float*)d_in[5];
    const float* b1     = (const float*)d_in[6];
    const float* W2     = (const float*)d_in[7];
    const float* b2     = (const float*)d_in[8];
    const float* Wih    = (const float*)d_in[9];
    const float* Whh    = (const float*)d_in[10];
    const float* bih    = (const float*)d_in[11];
    const float* bhh    = (const float*)d_in[12];
    const float* gamma  = (const float*)d_in[13];
    const float* beta   = (const float*)d_in[14];
    float* out = (float*)d_out;

    const int QSMEM = 4 * 128 * STR2 * 2;    // 73728 B
    const int ESMEM = 2 * 128 * STRQ * 2;    // 102400 B
    cudaFuncSetAttribute(q_mma, cudaFuncAttributeMaxDynamicSharedMemorySize, QSMEM);
    cudaFuncSetAttribute(eh_mma, cudaFuncAttributeMaxDynamicSharedMemorySize, ESMEM);

    // launch #4 is the one ncu captures -> q_mma
    prep_kernel<<<64 + 512, 256>>>(node, edge, W1, W2, Wih, Whh);   // 1
    count_kernel<<<(NE + 255) / 256, 256>>>(src);                   // 2
    scan_kernel<<<1, 1024>>>();                                     // 3
    q_mma<<<dim3(QC / 128, NNP / 128), 256, QSMEM>>>();             // 4 <- profiled
    eh_mma<<<NEP / 128, 256, ESMEM>>>(b1);                          // 5
    scatter_kernel<<<(NE + 255) / 256, 256>>>(src);                 // 6
    msg_kernel<<<NN, 128>>>(node, b2, dst);                         // 7
    gru_ln_kernel<<<296, 256>>>(hidden, bih, bhh, gamma, beta, out);// 8
}

// round 11
// speedup vs baseline: 2.6207x; 1.1616x over previous
#include <cuda_runtime.h>
#include <cuda_bf16.h>
#include <cuda_fp16.h>
#include <math.h>
#include <cstdint>

#define H 64
#define NN 12000
#define NE 50000
#define EHD 128          // 2H
#define QC 8192          // H * 2H
#define NNP 12032        // NN padded to 128
#define NEP 50048        // NE padded to 128
#define KS 192           // split-K (hi|hi|lo)
#define STRQ 200         // smem row stride (bf16) for eh_mma
#define STR2 72          // smem row stride (bf16) for q_mma chunks
#define QSLOT 72         // halves per thread slot in msg staging (144B, 16B-aligned)

// ---------------- scratch (device globals; allocation-free) ----------------
__device__ __align__(16) float g_eh[NE * EHD];          // 25.6 MB
__device__ __align__(16) __half g_q[(size_t)NN * QC];   // 196 MB (fp16)
__device__ float g_agg[NN * H];
__device__ float g_WihT[64 * 192];
__device__ float g_WhhT[64 * 192];
__device__ __align__(16) __nv_bfloat16 g_Asplit[NNP * KS];   // node  hi|hi|lo
__device__ __align__(16) __nv_bfloat16 g_Bsplit[QC * KS];    // W2^T  hi|lo|hi
__device__ __align__(16) __nv_bfloat16 g_Esplit[NEP * KS];   // edge  hi|hi|lo
__device__ __align__(16) __nv_bfloat16 g_W1split[128 * KS];  // W1    hi|lo|hi
__device__ int g_cnt[NN];
__device__ int g_off[NN + 1];
__device__ int g_cur[NN];
__device__ int g_elist[NE];

__device__ __forceinline__ uint32_t smem_to_u32(const void* p) {
    uint32_t a;
    asm("{ .reg .u64 t; cvta.to.shared.u64 t, %1; cvt.u32.u64 %0, t; }" : "=r"(a) : "l"(p));
    return a;
}
__device__ __forceinline__ void cp16(void* s, const void* g) {
    uint32_t sa = smem_to_u32(s);
    asm volatile("cp.async.cg.shared.global [%0], [%1], 16;" :: "r"(sa), "l"(g));
}
__device__ __forceinline__ void cp16a(uint32_t sa, const void* g) {
    asm volatile("cp.async.cg.shared.global [%0], [%1], 16;" :: "r"(sa), "l"(g));
}

// ---------------- 1: PREP (fused zero + transposes + bf16 splits) -----------
__global__ __launch_bounds__(256) void prep_kernel(const float* __restrict__ node,
                                                   const float* __restrict__ edge,
                                                   const float* __restrict__ W1,
                                                   const float* __restrict__ W2,
                                                   const float* __restrict__ Wih,
                                                   const float* __restrict__ Whh) {
    __shared__ float Ws[64 * 128];
    int b = blockIdx.x;
    int t = threadIdx.x;
    if (b < 64) {
        int n0 = b * 128;
        for (int j = t; j < 8192; j += 256) {
            int k = j >> 7, n = j & 127;
            Ws[k * 128 + n] = W2[(size_t)k * QC + n0 + n];
        }
        __syncthreads();
        for (int j = t; j < 8192; j += 256) {
            int n = j >> 6, k = j & 63;
            float x = Ws[k * 128 + n];
            __nv_bfloat16 hi = __float2bfloat16(x);
            __nv_bfloat16 lo = __float2bfloat16(x - __bfloat162float(hi));
            size_t base = (size_t)(n0 + n) * KS;
            g_Bsplit[base + k] = hi;
            g_Bsplit[base + 64 + k] = lo;
            g_Bsplit[base + 128 + k] = hi;
        }
        return;
    }
    int i0 = (b - 64) * 256 + t;
    int stride = (gridDim.x - 64) * 256;
    for (int j = i0; j < NN * H; j += stride) g_agg[j] = 0.f;
    for (int j = i0; j < NN; j += stride) g_cnt[j] = 0;
    for (int j = i0; j < 192 * 64; j += stride) {
        int r = j >> 6, h = j & 63;
        g_WihT[h * 192 + r] = Wih[j];
        g_WhhT[h * 192 + r] = Whh[j];
    }
    for (int j = i0; j < 128 * 64; j += stride) {
        int n = j >> 6, k = j & 63;
        float x = W1[j];
        __nv_bfloat16 hi = __float2bfloat16(x);
        __nv_bfloat16 lo = __float2bfloat16(x - __bfloat162float(hi));
        g_W1split[n * KS + k] = hi;
        g_W1split[n * KS + 64 + k] = lo;
        g_W1split[n * KS + 128 + k] = hi;
    }
    for (int j = i0; j < NNP * 64; j += stride) {
        int n = j >> 6, h = j & 63;
        float x = (n < NN) ? node[n * 64 + h] : 0.f;
        __nv_bfloat16 hi = __float2bfloat16(x);
        __nv_bfloat16 lo = __float2bfloat16(x - __bfloat162float(hi));
        g_Asplit[n * KS + h] = hi;
        g_Asplit[n * KS + 64 + h] = hi;
        g_Asplit[n * KS + 128 + h] = lo;
    }
    for (int j = i0; j < NEP * 64; j += stride) {
        int n = j >> 6, h = j & 63;
        float x = (n < NE) ? edge[n * 64 + h] : 0.f;
        __nv_bfloat16 hi = __float2bfloat16(x);
        __nv_bfloat16 lo = __float2bfloat16(x - __bfloat162float(hi));
        g_Esplit[n * KS + h] = hi;
        g_Esplit[n * KS + 64 + h] = hi;
        g_Esplit[n * KS + 128 + h] = lo;
    }
}

// ---------------- CSR by src ----------------
__global__ void count_kernel(const int* __restrict__ src) {
    int e = blockIdx.x * blockDim.x + threadIdx.x;
    if (e < NE) atomicAdd(&g_cnt[src[e]], 1);
}

__global__ void scan_kernel() {
    __shared__ int sm[1024];
    int tid = threadIdx.x;
    const int C = 12;
    int base = tid * C;
    int loc[C];
    int s = 0;
#pragma unroll
    for (int i = 0; i < C; i++) {
        int v = (base + i < NN) ? g_cnt[base + i] : 0;
        loc[i] = s;
        s += v;
    }
    sm[tid] = s;
    __syncthreads();
    for (int d = 1; d < 1024; d <<= 1) {
        int v = (tid >= d) ? sm[tid - d] : 0;
        __syncthreads();
        if (tid >= d) sm[tid] += v;
        __syncthreads();
    }
    int ex = sm[tid] - s;
#pragma unroll
    for (int i = 0; i < C; i++) {
        if (base + i < NN) {
            g_off[base + i] = ex + loc[i];
            g_cur[base + i] = ex + loc[i];
        }
    }
    if (tid == 1023) g_off[NN] = sm[1023];
}

__global__ void scatter_kernel(const int* __restrict__ src) {
    int e = blockIdx.x * blockDim.x + threadIdx.x;
    if (e < NE) {
        int p = atomicAdd(&g_cur[src[e]], 1);
        g_elist[p] = e;
    }
}

// ---------------- eh = relu(edge @ W1.T + b1) on mma.sync ----------------
__global__ __launch_bounds__(256, 2) void eh_mma(const float* __restrict__ b1) {
    extern __shared__ __nv_bfloat16 sme[];
    __nv_bfloat16* As = sme;               // [128][STRQ]
    __nv_bfloat16* Bs = sme + 128 * STRQ;  // [128][STRQ]
    int m0 = blockIdx.x * 128;
    int tid = threadIdx.x;

    for (int i = tid; i < 3072; i += 256) {
        int r = i / 24, c = i % 24;
        *reinterpret_cast<uint4*>(As + r * STRQ + c * 8) =
            reinterpret_cast<const uint4*>(g_Esplit + (size_t)(m0 + r) * KS)[c];
        *reinterpret_cast<uint4*>(Bs + r * STRQ + c * 8) =
            reinterpret_cast<const uint4*>(g_W1split + (size_t)r * KS)[c];
    }
    __syncthreads();

    int w = tid >> 5, lane = tid & 31;
    int wm = (w & 3) * 32, wn = (w >> 2) * 64;
    int g = lane >> 3;
    int arow = (lane & 7) + (g & 1) * 8, aka = (g >> 1) * 8;
    int brow = (lane & 7) + (g >> 1) * 8, bka = (g & 1) * 8;

    float acc[2][8][4];
#pragma unroll
    for (int im = 0; im < 2; im++)
#pragma unroll
        for (int jn = 0; jn < 8; jn++)
#pragma unroll
            for (int c = 0; c < 4; c++) acc[im][jn][c] = 0.f;

#pragma unroll
    for (int kk = 0; kk < 12; kk++) {
        int k0 = kk * 16;
        uint32_t a[2][4];
#pragma unroll
        for (int im = 0; im < 2; im++) {
            uint32_t addr = smem_to_u32(As + (wm + im * 16 + arow) * STRQ + k0 + aka);
            asm volatile("ldmatrix.sync.aligned.m8n8.x4.shared.b16 {%0,%1,%2,%3}, [%4];"
                         : "=r"(a[im][0]), "=r"(a[im][1]), "=r"(a[im][2]), "=r"(a[im][3])
                         : "r"(addr));
        }
#pragma unroll
        for (int jb = 0; jb < 4; jb++) {
            uint32_t b0, b1r, b2, b3;
            uint32_t addr = smem_to_u32(Bs + (wn + jb * 16 + brow) * STRQ + k0 + bka);
            asm volatile("ldmatrix.sync.aligned.m8n8.x4.shared.b16 {%0,%1,%2,%3}, [%4];"
                         : "=r"(b0), "=r"(b1r), "=r"(b2), "=r"(b3) : "r"(addr));
#pragma unroll
            for (int im = 0; im < 2; im++) {
                asm volatile(
                    "mma.sync.aligned.m16n8k16.row.col.f32.bf16.bf16.f32 "
                    "{%0,%1,%2,%3}, {%4,%5,%6,%7}, {%8,%9}, {%0,%1,%2,%3};"
                    : "+f"(acc[im][jb * 2][0]), "+f"(acc[im][jb * 2][1]),
                      "+f"(acc[im][jb * 2][2]), "+f"(acc[im][jb * 2][3])
                    : "r"(a[im][0]), "r"(a[im][1]), "r"(a[im][2]), "r"(a[im][3]),
                      "r"(b0), "r"(b1r));
                asm volatile(
                    "mma.sync.aligned.m16n8k16.row.col.f32.bf16.bf16.f32 "
                    "{%0,%1,%2,%3}, {%4,%5,%6,%7}, {%8,%9}, {%0,%1,%2,%3};"
                    : "+f"(acc[im][jb * 2 + 1][0]), "+f"(acc[im][jb * 2 + 1][1]),
                      "+f"(acc[im][jb * 2 + 1][2]), "+f"(acc[im][jb * 2 + 1][3])
                    : "r"(a[im][0]), "r"(a[im][1]), "r"(a[im][2]), "r"(a[im][3]),
                      "r"(b2), "r"(b3));
            }
        }
    }

#pragma unroll
    for (int im = 0; im < 2; im++) {
        int m = m0 + wm + im * 16 + (lane >> 2);
#pragma unroll
        for (int jn = 0; jn < 8; jn++) {
            int c = wn + jn * 8 + (lane & 3) * 2;
            float bb0 = b1[c], bb1 = b1[c + 1];
            if (m < NE)
                *reinterpret_cast<float2*>(&g_eh[(size_t)m * EHD + c]) =
                    make_float2(fmaxf(acc[im][jn][0] + bb0, 0.f),
                                fmaxf(acc[im][jn][1] + bb1, 0.f));
            if (m + 8 < NE)
                *reinterpret_cast<float2*>(&g_eh[(size_t)(m + 8) * EHD + c]) =
                    make_float2(fmaxf(acc[im][jn][2] + bb0, 0.f),
                                fmaxf(acc[im][jn][3] + bb1, 0.f));
        }
    }
}

// ---------------- q GEMM on mma.sync, cp.async pipelined, fp16 out ----------
__global__ __launch_bounds__(256, 2) void q_mma() {
    extern __shared__ __nv_bfloat16 smq[];
    __nv_bfloat16* As = smq;               // [2][128][STR2]
    __nv_bfloat16* Bs = smq + 2 * 128 * STR2;
    int n0 = blockIdx.x * 128, m0 = blockIdx.y * 128;
    int tid = threadIdx.x;

    int w = tid >> 5, lane = tid & 31;
    int wm = (w & 3) * 32, wn = (w >> 2) * 64;
    int g = lane >> 3;
    int arow = (lane & 7) + (g & 1) * 8, aka = (g >> 1) * 8;
    int brow = (lane & 7) + (g >> 1) * 8, bka = (g & 1) * 8;

    float acc[2][8][4];
#pragma unroll
    for (int im = 0; im < 2; im++)
#pragma unroll
        for (int jn = 0; jn < 8; jn++)
#pragma unroll
            for (int c = 0; c < 4; c++) acc[im][jn][c] = 0.f;

#define STAGE(c) do { \
        int _buf = (c) & 1; \
        __nv_bfloat16* _Ad = As + _buf * 128 * STR2; \
        __nv_bfloat16* _Bd = Bs + _buf * 128 * STR2; \
        const __nv_bfloat16* _Ag = g_Asplit + (size_t)m0 * KS + (c) * 64; \
        const __nv_bfloat16* _Bg = g_Bsplit + (size_t)n0 * KS + (c) * 64; \
        _Pragma("unroll") \
        for (int _i = 0; _i < 4; _i++) { \
            int _idx = tid + _i * 256; \
            int _r = _idx >> 3, _j = _idx & 7; \
            cp16(_Ad + _r * STR2 + _j * 8, _Ag + (size_t)_r * KS + _j * 8); \
            cp16(_Bd + _r * STR2 + _j * 8, _Bg + (size_t)_r * KS + _j * 8); \
        } \
        asm volatile("cp.async.commit_group;"); \
    } while (0)

    STAGE(0);
#pragma unroll
    for (int c = 0; c < 3; c++) {
        if (c + 1 < 3) STAGE(c + 1);
        if (c + 1 < 3) asm volatile("cp.async.wait_group 1;");
        else           asm volatile("cp.async.wait_group 0;");
        __syncthreads();
        const __nv_bfloat16* Ab = As + (c & 1) * 128 * STR2;
        const __nv_bfloat16* Bb = Bs + (c & 1) * 128 * STR2;
#pragma unroll
        for (int ks = 0; ks < 4; ks++) {
            int k0 = ks * 16;
            uint32_t a[2][4];
#pragma unroll
            for (int im = 0; im < 2; im++) {
                uint32_t addr = smem_to_u32(Ab + (wm + im * 16 + arow) * STR2 + k0 + aka);
                asm volatile("ldmatrix.sync.aligned.m8n8.x4.shared.b16 {%0,%1,%2,%3}, [%4];"
                             : "=r"(a[im][0]), "=r"(a[im][1]), "=r"(a[im][2]), "=r"(a[im][3])
                             : "r"(addr));
            }
#pragma unroll
            for (int jb = 0; jb < 4; jb++) {
                uint32_t b0, b1, b2, b3;
                uint32_t addr = smem_to_u32(Bb + (wn + jb * 16 + brow) * STR2 + k0 + bka);
                asm volatile("ldmatrix.sync.aligned.m8n8.x4.shared.b16 {%0,%1,%2,%3}, [%4];"
                             : "=r"(b0), "=r"(b1), "=r"(b2), "=r"(b3) : "r"(addr));
#pragma unroll
                for (int im = 0; im < 2; im++) {
                    asm volatile(
                        "mma.sync.aligned.m16n8k16.row.col.f32.bf16.bf16.f32 "
                        "{%0,%1,%2,%3}, {%4,%5,%6,%7}, {%8,%9}, {%0,%1,%2,%3};"
                        : "+f"(acc[im][jb * 2][0]), "+f"(acc[im][jb * 2][1]),
                          "+f"(acc[im][jb * 2][2]), "+f"(acc[im][jb * 2][3])
                        : "r"(a[im][0]), "r"(a[im][1]), "r"(a[im][2]), "r"(a[im][3]),
                          "r"(b0), "r"(b1));
                    asm volatile(
                        "mma.sync.aligned.m16n8k16.row.col.f32.bf16.bf16.f32 "
                        "{%0,%1,%2,%3}, {%4,%5,%6,%7}, {%8,%9}, {%0,%1,%2,%3};"
                        : "+f"(acc[im][jb * 2 + 1][0]), "+f"(acc[im][jb * 2 + 1][1]),
                          "+f"(acc[im][jb * 2 + 1][2]), "+f"(acc[im][jb * 2 + 1][3])
                        : "r"(a[im][0]), "r"(a[im][1]), "r"(a[im][2]), "r"(a[im][3]),
                          "r"(b2), "r"(b3));
                }
            }
        }
        __syncthreads();
    }
#undef STAGE

#pragma unroll
    for (int im = 0; im < 2; im++) {
        int m = m0 + wm + im * 16 + (lane >> 2);
#pragma unroll
        for (int jn = 0; jn < 8; jn++) {
            int c = n0 + wn + jn * 8 + (lane & 3) * 2;
            if (m < NN)
                *reinterpret_cast<__half2*>(&g_q[(size_t)m * QC + c]) =
                    __floats2half2_rn(acc[im][jn][0], acc[im][jn][1]);
            if (m + 8 < NN)
                *reinterpret_cast<__half2*>(&g_q[(size_t)(m + 8) * QC + c]) =
                    __floats2half2_rn(acc[im][jn][2], acc[im][jn][3]);
        }
    }
}

// ---------------- msg v2: register-resident q, chunked edge prefetch --------
// thread t owns q halves [t*64, t*64+64)  ==  (k = t>>1, c-half = t&1)
__global__ __launch_bounds__(128) void msg_kernel(const float* __restrict__ node,
                                                  const float* __restrict__ b2,
                                                  const int* __restrict__ dst) {
    __shared__ __align__(16) __half q_h[128 * QSLOT];   // 18.4 KB
    __shared__ float x_s[64];
    __shared__ float bb_s[64];
    __shared__ int e_s[32];
    __shared__ int d_s[32];
    int n = blockIdx.x;
    int t = threadIdx.x;

    int beg = g_off[n], end = g_off[n + 1];
    if (beg == end) return;

    // stage q row raw (fp16): 1024 uint4, gmem-coalesced; smem slot per thread
    const uint4* qn = reinterpret_cast<const uint4*>(g_q + (size_t)n * QC);
    uint32_t qbase = smem_to_u32(q_h);
#pragma unroll
    for (int i = 0; i < 8; i++) {
        int j = t + i * 128;
        uint32_t dstb = qbase + (uint32_t)((j >> 3) * (QSLOT * 2) + (j & 7) * 16);
        cp16a(dstb, qn + j);
    }
    asm volatile("cp.async.commit_group;");
    if (t < 64) x_s[t] = node[n * 64 + t];
    asm volatile("cp.async.wait_group 0;");
    __syncthreads();

    // bias term (needs x_s)
    if (t < 64) {
        float bb = 0.f;
#pragma unroll 8
        for (int h = 0; h < 64; h++) bb = fmaf(x_s[h], b2[h * 64 + t], bb);
        bb_s[t] = bb;
    }

    // my 64 q values -> registers (8 LDS.128 + convert)
    float qf[64];
    {
        const uint4* myq = reinterpret_cast<const uint4*>(q_h + t * QSLOT);
#pragma unroll
        for (int i = 0; i < 8; i++) {
            uint4 v = myq[i];
            const __half2* h2 = reinterpret_cast<const __half2*>(&v);
#pragma unroll
            for (int p = 0; p < 4; p++) {
                float2 f = __half22float2(h2[p]);
                qf[i * 8 + p * 2] = f.x;
                qf[i * 8 + p * 2 + 1] = f.y;
            }
        }
    }
    __syncthreads();   // bb_s ready

    int k = t >> 1, half = t & 1;
    float mybb = bb_s[k];

    for (int cb = beg; cb < end; cb += 32) {
        int cnt = end - cb;
        if (cnt > 32) cnt = 32;
        __syncthreads();
        if (t < cnt) {
            int e = g_elist[cb + t];
            e_s[t] = e;
            d_s[t] = dst[e];
        }
        __syncthreads();
        for (int ii = 0; ii < cnt; ii++) {
            int e = e_s[ii];
            const float4* ep = reinterpret_cast<const float4*>(g_eh + (size_t)e * EHD) + half * 16;
            float acc = 0.f;
#pragma unroll
            for (int g = 0; g < 16; g++) {
                float4 ev = ep[g];
                acc = fmaf(ev.x, qf[g * 4 + 0], acc);
                acc = fmaf(ev.y, qf[g * 4 + 1], acc);
                acc = fmaf(ev.z, qf[g * 4 + 2], acc);
                acc = fmaf(ev.w, qf[g * 4 + 3], acc);
            }
            acc += __shfl_xor_sync(0xffffffffu, acc, 1);
            if (half == 0)
                atomicAdd(&g_agg[d_s[ii] * 64 + k], acc + mybb);
        }
    }
}

// ---------------- relu(agg) -> GRU -> LayerNorm ----------------
__global__ __launch_bounds__(256) void gru_ln_kernel(const float* __restrict__ hidden,
                                                     const float* __restrict__ bih,
                                                     const float* __restrict__ bhh,
                                                     const float* __restrict__ gamma,
                                                     const float* __restrict__ beta,
                                                     float* __restrict__ out) {
    __shared__ float xs[4][64], hs[4][64];
    __shared__ float redA[8], redB[8];
    int t = threadIdx.x;
    int sub = t >> 6, k = t & 63;
    int wid = t >> 5, lane = t & 31;
    float bi0 = bih[k], bi1 = bih[64 + k], bi2 = bih[128 + k];
    float bh0 = bhh[k], bh1 = bhh[64 + k], bh2 = bhh[128 + k];
    float gm = gamma[k], bt = beta[k];

    for (int n0 = blockIdx.x * 4; n0 < NN; n0 += gridDim.x * 4) {
        int n = n0 + sub;
        float x = fmaxf(g_agg[n * 64 + k], 0.f);
        float hv = hidden[n * 64 + k];
        xs[sub][k] = x;
        hs[sub][k] = hv;
        __syncthreads();
        float gi0 = bi0, gi1 = bi1, gi2 = bi2;
        float gh0 = bh0, gh1 = bh1, gh2 = bh2;
#pragma unroll 8
        for (int h = 0; h < 64; h++) {
            float xv = xs[sub][h], hh = hs[sub][h];
            const float* wi = &g_WihT[h * 192];
            const float* wh = &g_WhhT[h * 192];
            gi0 = fmaf(xv, wi[k], gi0);
            gi1 = fmaf(xv, wi[64 + k], gi1);
            gi2 = fmaf(xv, wi[128 + k], gi2);
            gh0 = fmaf(hh, wh[k], gh0);
            gh1 = fmaf(hh, wh[64 + k], gh1);
            gh2 = fmaf(hh, wh[128 + k], gh2);
        }
        float r = 1.f / (1.f + expf(-(gi0 + gh0)));
        float z = 1.f / (1.f + expf(-(gi1 + gh1)));
        float nn2 = tanhf(gi2 + r * gh2);
        float o = (1.f - z) * nn2 + z * hv;

        float s1 = o, s2 = o * o;
#pragma unroll
        for (int d = 16; d > 0; d >>= 1) {
            s1 += __shfl_xor_sync(0xffffffffu, s1, d);
            s2 += __shfl_xor_sync(0xffffffffu, s2, d);
        }
        if (lane == 0) { redA[wid] = s1; redB[wid] = s2; }
        __syncthreads();
        float S1 = redA[sub * 2] + redA[sub * 2 + 1];
        float S2 = redB[sub * 2] + redB[sub * 2 + 1];
        float mu = S1 * 0.015625f;
        float var = S2 * 0.015625f - mu * mu;
        out[n * 64 + k] = (o - mu) * rsqrtf(var + 1e-5f) * gm + bt;
        __syncthreads();
    }
}

// ---------------- launch ----------------
extern "C" void kernel_launch(void* const* d_in, const int* in_sizes, int n_in,
                              void* d_out, int out_size) {
    const float* node   = (const float*)d_in[0];
    const float* edge   = (const float*)d_in[1];
    const float* hidden = (const float*)d_in[2];
    const int*   src    = (const int*)d_in[3];
    const int*   dst    = (const int*)d_in[4];
    const float* W1     = (const float*)d_in[5];
    const float* b1     = (const float*)d_in[6];
    const float* W2     = (const float*)d_in[7];
    const float* b2     = (const float*)d_in[8];
    const float* Wih    = (const float*)d_in[9];
    const float* Whh    = (const float*)d_in[10];
    const float* bih    = (const float*)d_in[11];
    const float* bhh    = (const float*)d_in[12];
    const float* gamma  = (const float*)d_in[13];
    const float* beta   = (const float*)d_in[14];
    float* out = (float*)d_out;

    const int QSMEM = 4 * 128 * STR2 * 2;    // 73728 B
    const int ESMEM = 2 * 128 * STRQ * 2;    // 102400 B
    cudaFuncSetAttribute(q_mma, cudaFuncAttributeMaxDynamicSharedMemorySize, QSMEM);
    cudaFuncSetAttribute(eh_mma, cudaFuncAttributeMaxDynamicSharedMemorySize, ESMEM);

    // launch #4 is the one ncu captures -> eh_mma (unmeasured so far)
    prep_kernel<<<64 + 512, 256>>>(node, edge, W1, W2, Wih, Whh);   // 1
    count_kernel<<<(NE + 255) / 256, 256>>>(src);                   // 2
    scan_kernel<<<1, 1024>>>();                                     // 3
    eh_mma<<<NEP / 128, 256, ESMEM>>>(b1);                          // 4 <- profiled
    q_mma<<<dim3(QC / 128, NNP / 128), 256, QSMEM>>>();             // 5
    scatter_kernel<<<(NE + 255) / 256, 256>>>(src);                 // 6
    msg_kernel<<<NN, 128>>>(node, b2, dst);                         // 7
    gru_ln_kernel<<<296, 256>>>(hidden, bih, bhh, gamma, beta, out);// 8
}

// round 12
// speedup vs baseline: 2.8685x; 1.0946x over previous
#include <cuda_runtime.h>
#include <cuda_bf16.h>
#include <cuda_fp16.h>
#include <math.h>
#include <cstdint>

#define H 64
#define NN 12000
#define NE 50000
#define EHD 128          // 2H
#define QC 8192          // H * 2H
#define NNP 12032        // NN padded to 128
#define NEP 50048        // NE padded to 128
#define KS 192           // split-K (hi|hi|lo)
#define STRQ 200         // smem row stride (bf16) for eh_mma
#define STR2 72          // smem row stride (bf16) for q_mma chunks
#define QSLOT 72         // halves per thread slot in msg staging

// ---------------- scratch (device globals; allocation-free) ----------------
__device__ __align__(16) float g_eh[NE * EHD];          // 25.6 MB
__device__ __align__(16) __half g_q[(size_t)NN * QC];   // 196 MB (fp16)
__device__ float g_agg[NN * H];
__device__ float g_WihT[64 * 192];
__device__ float g_WhhT[64 * 192];
__device__ __align__(16) __nv_bfloat16 g_Asplit[NNP * KS];   // node  hi|hi|lo
__device__ __align__(16) __nv_bfloat16 g_Bsplit[QC * KS];    // W2^T  hi|lo|hi
__device__ __align__(16) __nv_bfloat16 g_Esplit[NEP * KS];   // edge  hi|hi|lo
__device__ __align__(16) __nv_bfloat16 g_W1split[128 * KS];  // W1    hi|lo|hi
__device__ int g_cnt[NN];
__device__ int g_off[NN + 1];
__device__ int g_cur[NN];
__device__ int g_elist[NE];

__device__ __forceinline__ uint32_t smem_to_u32(const void* p) {
    uint32_t a;
    asm("{ .reg .u64 t; cvta.to.shared.u64 t, %1; cvt.u32.u64 %0, t; }" : "=r"(a) : "l"(p));
    return a;
}
__device__ __forceinline__ void cp16(void* s, const void* g) {
    uint32_t sa = smem_to_u32(s);
    asm volatile("cp.async.cg.shared.global [%0], [%1], 16;" :: "r"(sa), "l"(g));
}
__device__ __forceinline__ void cp16a(uint32_t sa, const void* g) {
    asm volatile("cp.async.cg.shared.global [%0], [%1], 16;" :: "r"(sa), "l"(g));
}
__device__ __forceinline__ uint32_t pack_bf2(float a, float b) {
    __nv_bfloat162 v = __floats2bfloat162_rn(a, b);
    return *reinterpret_cast<uint32_t*>(&v);
}

// ---------------- 1: PREP (fused zero + transposes + bf16 splits) -----------
__global__ __launch_bounds__(256) void prep_kernel(const float* __restrict__ node,
                                                   const float* __restrict__ edge,
                                                   const float* __restrict__ W1,
                                                   const float* __restrict__ W2,
                                                   const float* __restrict__ Wih,
                                                   const float* __restrict__ Whh) {
    __shared__ float Ws[64 * 128];
    int b = blockIdx.x;
    int t = threadIdx.x;
    if (b < 64) {
        int n0 = b * 128;
        for (int j = t; j < 8192; j += 256) {
            int k = j >> 7, n = j & 127;
            Ws[k * 128 + n] = W2[(size_t)k * QC + n0 + n];
        }
        __syncthreads();
        for (int j = t; j < 8192; j += 256) {
            int n = j >> 6, k = j & 63;
            float x = Ws[k * 128 + n];
            __nv_bfloat16 hi = __float2bfloat16(x);
            __nv_bfloat16 lo = __float2bfloat16(x - __bfloat162float(hi));
            size_t base = (size_t)(n0 + n) * KS;
            g_Bsplit[base + k] = hi;
            g_Bsplit[base + 64 + k] = lo;
            g_Bsplit[base + 128 + k] = hi;
        }
        return;
    }
    int i0 = (b - 64) * 256 + t;
    int stride = (gridDim.x - 64) * 256;
    for (int j = i0; j < NN * H; j += stride) g_agg[j] = 0.f;
    for (int j = i0; j < NN; j += stride) g_cnt[j] = 0;
    for (int j = i0; j < 192 * 64; j += stride) {
        int r = j >> 6, h = j & 63;
        g_WihT[h * 192 + r] = Wih[j];
        g_WhhT[h * 192 + r] = Whh[j];
    }
    for (int j = i0; j < 128 * 64; j += stride) {
        int n = j >> 6, k = j & 63;
        float x = W1[j];
        __nv_bfloat16 hi = __float2bfloat16(x);
        __nv_bfloat16 lo = __float2bfloat16(x - __bfloat162float(hi));
        g_W1split[n * KS + k] = hi;
        g_W1split[n * KS + 64 + k] = lo;
        g_W1split[n * KS + 128 + k] = hi;
    }
    // node split (vectorized: h-pairs, bfloat162 stores)
    for (int j = i0; j < NNP * 32; j += stride) {
        int n = j >> 5, hp = j & 31;
        float2 x = (n < NN) ? reinterpret_cast<const float2*>(node)[n * 32 + hp]
                            : make_float2(0.f, 0.f);
        float h0 = __bfloat162float(__float2bfloat16(x.x));
        float h1 = __bfloat162float(__float2bfloat16(x.y));
        uint32_t hi2 = pack_bf2(x.x, x.y);
        uint32_t lo2 = pack_bf2(x.x - h0, x.y - h1);
        uint32_t* base = reinterpret_cast<uint32_t*>(g_Asplit + (size_t)n * KS);
        base[hp] = hi2;
        base[32 + hp] = hi2;
        base[64 + hp] = lo2;
    }
    // edge split (vectorized)
    for (int j = i0; j < NEP * 32; j += stride) {
        int n = j >> 5, hp = j & 31;
        float2 x = (n < NE) ? reinterpret_cast<const float2*>(edge)[n * 32 + hp]
                            : make_float2(0.f, 0.f);
        float h0 = __bfloat162float(__float2bfloat16(x.x));
        float h1 = __bfloat162float(__float2bfloat16(x.y));
        uint32_t hi2 = pack_bf2(x.x, x.y);
        uint32_t lo2 = pack_bf2(x.x - h0, x.y - h1);
        uint32_t* base = reinterpret_cast<uint32_t*>(g_Esplit + (size_t)n * KS);
        base[hp] = hi2;
        base[32 + hp] = hi2;
        base[64 + hp] = lo2;
    }
}

// ---------------- CSR by src ----------------
__global__ void count_kernel(const int* __restrict__ src) {
    int e = blockIdx.x * blockDim.x + threadIdx.x;
    if (e < NE) atomicAdd(&g_cnt[src[e]], 1);
}

__global__ void scan_kernel() {
    __shared__ int sm[1024];
    int tid = threadIdx.x;
    const int C = 12;
    int base = tid * C;
    int loc[C];
    int s = 0;
#pragma unroll
    for (int i = 0; i < C; i++) {
        int v = (base + i < NN) ? g_cnt[base + i] : 0;
        loc[i] = s;
        s += v;
    }
    sm[tid] = s;
    __syncthreads();
    for (int d = 1; d < 1024; d <<= 1) {
        int v = (tid >= d) ? sm[tid - d] : 0;
        __syncthreads();
        if (tid >= d) sm[tid] += v;
        __syncthreads();
    }
    int ex = sm[tid] - s;
#pragma unroll
    for (int i = 0; i < C; i++) {
        if (base + i < NN) {
            g_off[base + i] = ex + loc[i];
            g_cur[base + i] = ex + loc[i];
        }
    }
    if (tid == 1023) g_off[NN] = sm[1023];
}

__global__ void scatter_kernel(const int* __restrict__ src) {
    int e = blockIdx.x * blockDim.x + threadIdx.x;
    if (e < NE) {
        int p = atomicAdd(&g_cur[src[e]], 1);
        g_elist[p] = e;
    }
}

// ---------------- eh = relu(edge @ W1.T + b1) on mma.sync ----------------
__global__ __launch_bounds__(256, 2) void eh_mma(const float* __restrict__ b1) {
    extern __shared__ __nv_bfloat16 sme[];
    __nv_bfloat16* As = sme;               // [128][STRQ]
    __nv_bfloat16* Bs = sme + 128 * STRQ;  // [128][STRQ]
    int m0 = blockIdx.x * 128;
    int tid = threadIdx.x;

    for (int i = tid; i < 3072; i += 256) {
        int r = i / 24, c = i % 24;
        *reinterpret_cast<uint4*>(As + r * STRQ + c * 8) =
            reinterpret_cast<const uint4*>(g_Esplit + (size_t)(m0 + r) * KS)[c];
        *reinterpret_cast<uint4*>(Bs + r * STRQ + c * 8) =
            reinterpret_cast<const uint4*>(g_W1split + (size_t)r * KS)[c];
    }
    __syncthreads();

    int w = tid >> 5, lane = tid & 31;
    int wm = (w & 3) * 32, wn = (w >> 2) * 64;
    int g = lane >> 3;
    int arow = (lane & 7) + (g & 1) * 8, aka = (g >> 1) * 8;
    int brow = (lane & 7) + (g >> 1) * 8, bka = (g & 1) * 8;

    float acc[2][8][4];
#pragma unroll
    for (int im = 0; im < 2; im++)
#pragma unroll
        for (int jn = 0; jn < 8; jn++)
#pragma unroll
            for (int c = 0; c < 4; c++) acc[im][jn][c] = 0.f;

#pragma unroll
    for (int kk = 0; kk < 12; kk++) {
        int k0 = kk * 16;
        uint32_t a[2][4];
#pragma unroll
        for (int im = 0; im < 2; im++) {
            uint32_t addr = smem_to_u32(As + (wm + im * 16 + arow) * STRQ + k0 + aka);
            asm volatile("ldmatrix.sync.aligned.m8n8.x4.shared.b16 {%0,%1,%2,%3}, [%4];"
                         : "=r"(a[im][0]), "=r"(a[im][1]), "=r"(a[im][2]), "=r"(a[im][3])
                         : "r"(addr));
        }
#pragma unroll
        for (int jb = 0; jb < 4; jb++) {
            uint32_t b0, b1r, b2, b3;
            uint32_t addr = smem_to_u32(Bs + (wn + jb * 16 + brow) * STRQ + k0 + bka);
            asm volatile("ldmatrix.sync.aligned.m8n8.x4.shared.b16 {%0,%1,%2,%3}, [%4];"
                         : "=r"(b0), "=r"(b1r), "=r"(b2), "=r"(b3) : "r"(addr));
#pragma unroll
            for (int im = 0; im < 2; im++) {
                asm volatile(
                    "mma.sync.aligned.m16n8k16.row.col.f32.bf16.bf16.f32 "
                    "{%0,%1,%2,%3}, {%4,%5,%6,%7}, {%8,%9}, {%0,%1,%2,%3};"
                    : "+f"(acc[im][jb * 2][0]), "+f"(acc[im][jb * 2][1]),
                      "+f"(acc[im][jb * 2][2]), "+f"(acc[im][jb * 2][3])
                    : "r"(a[im][0]), "r"(a[im][1]), "r"(a[im][2]), "r"(a[im][3]),
                      "r"(b0), "r"(b1r));
                asm volatile(
                    "mma.sync.aligned.m16n8k16.row.col.f32.bf16.bf16.f32 "
                    "{%0,%1,%2,%3}, {%4,%5,%6,%7}, {%8,%9}, {%0,%1,%2,%3};"
                    : "+f"(acc[im][jb * 2 + 1][0]), "+f"(acc[im][jb * 2 + 1][1]),
                      "+f"(acc[im][jb * 2 + 1][2]), "+f"(acc[im][jb * 2 + 1][3])
                    : "r"(a[im][0]), "r"(a[im][1]), "r"(a[im][2]), "r"(a[im][3]),
                      "r"(b2), "r"(b3));
            }
        }
    }

#pragma unroll
    for (int im = 0; im < 2; im++) {
        int m = m0 + wm + im * 16 + (lane >> 2);
#pragma unroll
        for (int jn = 0; jn < 8; jn++) {
            int c = wn + jn * 8 + (lane & 3) * 2;
            float bb0 = b1[c], bb1 = b1[c + 1];
            if (m < NE)
                *reinterpret_cast<float2*>(&g_eh[(size_t)m * EHD + c]) =
                    make_float2(fmaxf(acc[im][jn][0] + bb0, 0.f),
                                fmaxf(acc[im][jn][1] + bb1, 0.f));
            if (m + 8 < NE)
                *reinterpret_cast<float2*>(&g_eh[(size_t)(m + 8) * EHD + c]) =
                    make_float2(fmaxf(acc[im][jn][2] + bb0, 0.f),
                                fmaxf(acc[im][jn][3] + bb1, 0.f));
        }
    }
}

// ---------------- q GEMM v3: 4 warps, 64x64 warp tiles, cp.async pipeline ---
// CTA 128x128 tile, 128 threads. ldmatrix/mma = 0.25 (was 0.375).
__global__ __launch_bounds__(128) void q_mma() {
    extern __shared__ __nv_bfloat16 smq[];
    __nv_bfloat16* As = smq;               // [2][128][STR2]
    __nv_bfloat16* Bs = smq + 2 * 128 * STR2;
    int n0 = blockIdx.x * 128, m0 = blockIdx.y * 128;
    int tid = threadIdx.x;

    int w = tid >> 5, lane = tid & 31;
    int wm = (w & 1) * 64, wn = (w >> 1) * 64;
    int g = lane >> 3;
    int arow = (lane & 7) + (g & 1) * 8, aka = (g >> 1) * 8;
    int brow = (lane & 7) + (g >> 1) * 8, bka = (g & 1) * 8;

    float acc[4][8][4];
#pragma unroll
    for (int im = 0; im < 4; im++)
#pragma unroll
        for (int jn = 0; jn < 8; jn++)
#pragma unroll
            for (int c = 0; c < 4; c++) acc[im][jn][c] = 0.f;

#define STAGE(c) do { \
        int _buf = (c) & 1; \
        __nv_bfloat16* _Ad = As + _buf * 128 * STR2; \
        __nv_bfloat16* _Bd = Bs + _buf * 128 * STR2; \
        const __nv_bfloat16* _Ag = g_Asplit + (size_t)m0 * KS + (c) * 64; \
        const __nv_bfloat16* _Bg = g_Bsplit + (size_t)n0 * KS + (c) * 64; \
        _Pragma("unroll") \
        for (int _i = 0; _i < 8; _i++) { \
            int _idx = tid + _i * 128; \
            int _r = _idx >> 3, _j = _idx & 7; \
            cp16(_Ad + _r * STR2 + _j * 8, _Ag + (size_t)_r * KS + _j * 8); \
            cp16(_Bd + _r * STR2 + _j * 8, _Bg + (size_t)_r * KS + _j * 8); \
        } \
        asm volatile("cp.async.commit_group;"); \
    } while (0)

    STAGE(0);
#pragma unroll
    for (int c = 0; c < 3; c++) {
        if (c + 1 < 3) STAGE(c + 1);
        if (c + 1 < 3) asm volatile("cp.async.wait_group 1;");
        else           asm volatile("cp.async.wait_group 0;");
        __syncthreads();
        const __nv_bfloat16* Ab = As + (c & 1) * 128 * STR2;
        const __nv_bfloat16* Bb = Bs + (c & 1) * 128 * STR2;
#pragma unroll
        for (int ks = 0; ks < 4; ks++) {
            int k0 = ks * 16;
            uint32_t a[4][4];
#pragma unroll
            for (int im = 0; im < 4; im++) {
                uint32_t addr = smem_to_u32(Ab + (wm + im * 16 + arow) * STR2 + k0 + aka);
                asm volatile("ldmatrix.sync.aligned.m8n8.x4.shared.b16 {%0,%1,%2,%3}, [%4];"
                             : "=r"(a[im][0]), "=r"(a[im][1]), "=r"(a[im][2]), "=r"(a[im][3])
                             : "r"(addr));
            }
#pragma unroll
            for (int jb = 0; jb < 4; jb++) {
                uint32_t b0, b1, b2, b3;
                uint32_t addr = smem_to_u32(Bb + (wn + jb * 16 + brow) * STR2 + k0 + bka);
                asm volatile("ldmatrix.sync.aligned.m8n8.x4.shared.b16 {%0,%1,%2,%3}, [%4];"
                             : "=r"(b0), "=r"(b1), "=r"(b2), "=r"(b3) : "r"(addr));
#pragma unroll
                for (int im = 0; im < 4; im++) {
                    asm volatile(
                        "mma.sync.aligned.m16n8k16.row.col.f32.bf16.bf16.f32 "
                        "{%0,%1,%2,%3}, {%4,%5,%6,%7}, {%8,%9}, {%0,%1,%2,%3};"
                        : "+f"(acc[im][jb * 2][0]), "+f"(acc[im][jb * 2][1]),
                          "+f"(acc[im][jb * 2][2]), "+f"(acc[im][jb * 2][3])
                        : "r"(a[im][0]), "r"(a[im][1]), "r"(a[im][2]), "r"(a[im][3]),
                          "r"(b0), "r"(b1));
                    asm volatile(
                        "mma.sync.aligned.m16n8k16.row.col.f32.bf16.bf16.f32 "
                        "{%0,%1,%2,%3}, {%4,%5,%6,%7}, {%8,%9}, {%0,%1,%2,%3};"
                        : "+f"(acc[im][jb * 2 + 1][0]), "+f"(acc[im][jb * 2 + 1][1]),
                          "+f"(acc[im][jb * 2 + 1][2]), "+f"(acc[im][jb * 2 + 1][3])
                        : "r"(a[im][0]), "r"(a[im][1]), "r"(a[im][2]), "r"(a[im][3]),
                          "r"(b2), "r"(b3));
                }
            }
        }
        __syncthreads();
    }
#undef STAGE

    // fp16 epilogue
#pragma unroll
    for (int im = 0; im < 4; im++) {
        int m = m0 + wm + im * 16 + (lane >> 2);
#pragma unroll
        for (int jn = 0; jn < 8; jn++) {
            int c = n0 + wn + jn * 8 + (lane & 3) * 2;
            if (m < NN)
                *reinterpret_cast<__half2*>(&g_q[(size_t)m * QC + c]) =
                    __floats2half2_rn(acc[im][jn][0], acc[im][jn][1]);
            if (m + 8 < NN)
                *reinterpret_cast<__half2*>(&g_q[(size_t)(m + 8) * QC + c]) =
                    __floats2half2_rn(acc[im][jn][2], acc[im][jn][3]);
        }
    }
}

// ---------------- msg: register-resident q, chunked edge prefetch -----------
__global__ __launch_bounds__(128) void msg_kernel(const float* __restrict__ node,
                                                  const float* __restrict__ b2,
                                                  const int* __restrict__ dst) {
    __shared__ __align__(16) __half q_h[128 * QSLOT];   // 18.4 KB
    __shared__ float x_s[64];
    __shared__ float bb_s[64];
    __shared__ int e_s[32];
    __shared__ int d_s[32];
    int n = blockIdx.x;
    int t = threadIdx.x;

    int beg = g_off[n], end = g_off[n + 1];
    if (beg == end) return;

    const uint4* qn = reinterpret_cast<const uint4*>(g_q + (size_t)n * QC);
    uint32_t qbase = smem_to_u32(q_h);
#pragma unroll
    for (int i = 0; i < 8; i++) {
        int j = t + i * 128;
        uint32_t dstb = qbase + (uint32_t)((j >> 3) * (QSLOT * 2) + (j & 7) * 16);
        cp16a(dstb, qn + j);
    }
    asm volatile("cp.async.commit_group;");
    if (t < 64) x_s[t] = node[n * 64 + t];
    asm volatile("cp.async.wait_group 0;");
    __syncthreads();

    if (t < 64) {
        float bb = 0.f;
#pragma unroll 8
        for (int h = 0; h < 64; h++) bb = fmaf(x_s[h], b2[h * 64 + t], bb);
        bb_s[t] = bb;
    }

    float qf[64];
    {
        const uint4* myq = reinterpret_cast<const uint4*>(q_h + t * QSLOT);
#pragma unroll
        for (int i = 0; i < 8; i++) {
            uint4 v = myq[i];
            const __half2* h2 = reinterpret_cast<const __half2*>(&v);
#pragma unroll
            for (int p = 0; p < 4; p++) {
                float2 f = __half22float2(h2[p]);
                qf[i * 8 + p * 2] = f.x;
                qf[i * 8 + p * 2 + 1] = f.y;
            }
        }
    }
    __syncthreads();

    int k = t >> 1, half = t & 1;
    float mybb = bb_s[k];

    for (int cb = beg; cb < end; cb += 32) {
        int cnt = end - cb;
        if (cnt > 32) cnt = 32;
        __syncthreads();
        if (t < cnt) {
            int e = g_elist[cb + t];
            e_s[t] = e;
            d_s[t] = dst[e];
        }
        __syncthreads();
        for (int ii = 0; ii < cnt; ii++) {
            int e = e_s[ii];
            const float4* ep = reinterpret_cast<const float4*>(g_eh + (size_t)e * EHD) + half * 16;
            float acc = 0.f;
#pragma unroll
            for (int g = 0; g < 16; g++) {
                float4 ev = ep[g];
                acc = fmaf(ev.x, qf[g * 4 + 0], acc);
                acc = fmaf(ev.y, qf[g * 4 + 1], acc);
                acc = fmaf(ev.z, qf[g * 4 + 2], acc);
                acc = fmaf(ev.w, qf[g * 4 + 3], acc);
            }
            acc += __shfl_xor_sync(0xffffffffu, acc, 1);
            if (half == 0)
                atomicAdd(&g_agg[d_s[ii] * 64 + k], acc + mybb);
        }
    }
}

// ---------------- relu(agg) -> GRU -> LayerNorm ----------------
__global__ __launch_bounds__(256) void gru_ln_kernel(const float* __restrict__ hidden,
                                                     const float* __restrict__ bih,
                                                     const float* __restrict__ bhh,
                                                     const float* __restrict__ gamma,
                                                     const float* __restrict__ beta,
                                                     float* __restrict__ out) {
    __shared__ float xs[4][64], hs[4][64];
    __shared__ float redA[8], redB[8];
    int t = threadIdx.x;
    int sub = t >> 6, k = t & 63;
    int wid = t >> 5, lane = t & 31;
    float bi0 = bih[k], bi1 = bih[64 + k], bi2 = bih[128 + k];
    float bh0 = bhh[k], bh1 = bhh[64 + k], bh2 = bhh[128 + k];
    float gm = gamma[k], bt = beta[k];

    for (int n0 = blockIdx.x * 4; n0 < NN; n0 += gridDim.x * 4) {
        int n = n0 + sub;
        float x = fmaxf(g_agg[n * 64 + k], 0.f);
        float hv = hidden[n * 64 + k];
        xs[sub][k] = x;
        hs[sub][k] = hv;
        __syncthreads();
        float gi0 = bi0, gi1 = bi1, gi2 = bi2;
        float gh0 = bh0, gh1 = bh1, gh2 = bh2;
#pragma unroll 8
        for (int h = 0; h < 64; h++) {
            float xv = xs[sub][h], hh = hs[sub][h];
            const float* wi = &g_WihT[h * 192];
            const float* wh = &g_WhhT[h * 192];
            gi0 = fmaf(xv, wi[k], gi0);
            gi1 = fmaf(xv, wi[64 + k], gi1);
            gi2 = fmaf(xv, wi[128 + k], gi2);
            gh0 = fmaf(hh, wh[k], gh0);
            gh1 = fmaf(hh, wh[64 + k], gh1);
            gh2 = fmaf(hh, wh[128 + k], gh2);
        }
        float r = 1.f / (1.f + expf(-(gi0 + gh0)));
        float z = 1.f / (1.f + expf(-(gi1 + gh1)));
        float nn2 = tanhf(gi2 + r * gh2);
        float o = (1.f - z) * nn2 + z * hv;

        float s1 = o, s2 = o * o;
#pragma unroll
        for (int d = 16; d > 0; d >>= 1) {
            s1 += __shfl_xor_sync(0xffffffffu, s1, d);
            s2 += __shfl_xor_sync(0xffffffffu, s2, d);
        }
        if (lane == 0) { redA[wid] = s1; redB[wid] = s2; }
        __syncthreads();
        float S1 = redA[sub * 2] + redA[sub * 2 + 1];
        float S2 = redB[sub * 2] + redB[sub * 2 + 1];
        float mu = S1 * 0.015625f;
        float var = S2 * 0.015625f - mu * mu;
        out[n * 64 + k] = (o - mu) * rsqrtf(var + 1e-5f) * gm + bt;
        __syncthreads();
    }
}

// ---------------- launch ----------------
extern "C" void kernel_launch(void* const* d_in, const int* in_sizes, int n_in,
                              void* d_out, int out_size) {
    const float* node   = (const float*)d_in[0];
    const float* edge   = (const float*)d_in[1];
    const float* hidden = (const float*)d_in[2];
    const int*   src    = (const int*)d_in[3];
    const int*   dst    = (const int*)d_in[4];
    const float* W1     = (const float*)d_in[5];
    const float* b1     = (const float*)d_in[6];
    const float* W2     = (const float*)d_in[7];
    const float* b2     = (const float*)d_in[8];
    const float* Wih    = (const float*)d_in[9];
    const float* Whh    = (const float*)d_in[10];
    const float* bih    = (const float*)d_in[11];
    const float* bhh    = (const float*)d_in[12];
    const float* gamma  = (const float*)d_in[13];
    const float* beta   = (const float*)d_in[14];
    float* out = (float*)d_out;

    const int QSMEM = 4 * 128 * STR2 * 2;    // 73728 B
    const int ESMEM = 2 * 128 * STRQ * 2;    // 102400 B
    cudaFuncSetAttribute(q_mma, cudaFuncAttributeMaxDynamicSharedMemorySize, QSMEM);
    cudaFuncSetAttribute(eh_mma, cudaFuncAttributeMaxDynamicSharedMemorySize, ESMEM);

    // launch #4 is the one ncu captures -> q_mma (to verify the L1 theory)
    prep_kernel<<<64 + 512, 256>>>(node, edge, W1, W2, Wih, Whh);   // 1
    count_kernel<<<(NE + 255) / 256, 256>>>(src);                   // 2
    scan_kernel<<<1, 1024>>>();                                     // 3
    q_mma<<<dim3(QC / 128, NNP / 128), 128, QSMEM>>>();             // 4 <- profiled
    eh_mma<<<NEP / 128, 256, ESMEM>>>(b1);                          // 5
    scatter_kernel<<<(NE + 255) / 256, 256>>>(src);                 // 6
    msg_kernel<<<NN, 128>>>(node, b2, dst);                         // 7
    gru_ln_kernel<<<296, 256>>>(hidden, bih, bhh, gamma, beta, out);// 8
}